// round 11
// baseline (speedup 1.0000x reference)
#include <cuda_runtime.h>
#include <cuda_bf16.h>
#include <cstdint>
#include <cstddef>

// ----------------------------------------------------------------------------
// SCNN via warp-level HMMA (mma.sync bf16, fp32 accum), persistent CTAs.
// R10 = R9 design + fixed L6 smem constant (MODE_IN=1, not 0 -> was >227KB and
// failed the launch/capture). Warp owns m32 (B-fragments reused across 2
// m-tiles); GEMM2 K-split over warp pairs with fp32 partial exchange; Y stored
// transposed [k][m] (coalesced sconv stores + ldmatrix.trans A loads).
// 384 threads (12 warps), M-tile = 192 rows, 1 CTA/SM.
// ----------------------------------------------------------------------------

#define NB_TOTAL 50000
#define NC 45
#define ND 90
#define NTT 384
#define MTILE 192
#define MSTR 200     // Y [k][m] column count (192 + 8 pad): 400B rows
#define B1STR  56    // B1 [n=96][k=48], 112B rows
#define B2STR 104    // B2 [n=48][k=96], 208B rows
#define EXGSTR 49    // exchange [row][49] fp32, odd stride -> conflict-free

__device__ float g_bufA[(size_t)NB_TOTAL * 64 * NC];
__device__ float g_bufB[(size_t)NB_TOTAL * 32 * NC];
__device__ __nv_bfloat16 g_B1h[96 * 48], g_B1l[96 * 48];
__device__ __nv_bfloat16 g_B2h[48 * 96], g_B2l[48 * 96];

// ---------------- smem layout (bytes) ---------------------------------------
#define OFF_B1H 0
#define OFF_B1L 10752
#define OFF_B2H 21504
#define OFF_B2L 31488
#define OFF_YH  41472          /* 48*200*2 = 19200 */
#define OFF_YL  60672
#define OFF_EXG 79872          /* 192*49*4 = 37632 */
#define OFF_W   117504
#define DB1 10752
#define DB2  9984
#define DYL 19200

__host__ __device__ constexpr int smem_total_c(int CIN, int COUT, int MODE_IN) {
    return OFF_W + COUT * (CIN * 5 + 1) * 4 +
           (MODE_IN == 0 ? NC * ((MTILE / COUT) * CIN + 4) * 4 : 0);
}

// ---------------- PTX helpers ----------------------------------------------
__device__ __forceinline__ uint32_t smem_u32(const void* p) {
    uint32_t a;
    asm("{ .reg .u64 t; cvta.to.shared.u64 t, %1; cvt.u32.u64 %0, t; }"
        : "=r"(a) : "l"(p));
    return a;
}
__device__ __forceinline__ void ldsm_x4(uint32_t* r, uint32_t addr) {
    asm volatile("ldmatrix.sync.aligned.m8n8.x4.shared.b16 {%0,%1,%2,%3}, [%4];"
                 : "=r"(r[0]), "=r"(r[1]), "=r"(r[2]), "=r"(r[3]) : "r"(addr));
}
__device__ __forceinline__ void ldsm_x4t(uint32_t* r, uint32_t addr) {
    asm volatile("ldmatrix.sync.aligned.m8n8.x4.trans.shared.b16 {%0,%1,%2,%3}, [%4];"
                 : "=r"(r[0]), "=r"(r[1]), "=r"(r[2]), "=r"(r[3]) : "r"(addr));
}
__device__ __forceinline__ void mma_bf16(float* c, const uint32_t* a,
                                         uint32_t b0, uint32_t b1) {
    asm volatile(
        "mma.sync.aligned.m16n8k16.row.col.f32.bf16.bf16.f32 "
        "{%0,%1,%2,%3}, {%4,%5,%6,%7}, {%8,%9}, {%0,%1,%2,%3};"
        : "+f"(c[0]), "+f"(c[1]), "+f"(c[2]), "+f"(c[3])
        : "r"(a[0]), "r"(a[1]), "r"(a[2]), "r"(a[3]), "r"(b0), "r"(b1));
}
__device__ __forceinline__ uint32_t pack2bf(__nv_bfloat16 a, __nv_bfloat16 b) {
    return (uint32_t)__bfloat16_as_ushort(a) |
           ((uint32_t)__bfloat16_as_ushort(b) << 16);
}

// ---------------- problem constants -----------------------------------------
__host__ __device__ __forceinline__ constexpr int ggrp(int k) {
    return (k < 1) ? 0 : (k < 6) ? 1 : (k < 15) ? 2 : (k < 28) ? 3 : 4;
}
__device__ __forceinline__ float scl_of(int k) {
    const int g = ggrp(k);
    return g == 0 ? 1.77245385090552f
         : g == 1 ? 0.79266545952121f
         : g == 2 ? 0.59081795030184f
         : g == 3 ? 0.49159027f
         :          0.42988321f;
}

// ---------------- setup: pre-split B matrices to bf16 hi/lo -----------------
__global__ void build_B(const float* __restrict__ sft,
                        const float* __restrict__ isft) {
    const int tid = threadIdx.x;
    for (int i = tid; i < 96 * 48; i += 256) {     // B1[n=p(96)][k(48)]
        int n = i / 48, k = i - n * 48;
        float v = (n < ND && k < NC) ? isft[n * NC + k] : 0.f;
        __nv_bfloat16 hi = __float2bfloat16(v);
        g_B1h[i] = hi;
        g_B1l[i] = __float2bfloat16(v - __bfloat162float(hi));
    }
    for (int i = tid; i < 48 * 96; i += 256) {     // B2[n=k(48)][k=p(96)]
        int n = i / 96, p = i - n * 96;
        float v = (n < NC && p < ND) ? sft[n * ND + p] : 0.f;
        __nv_bfloat16 hi = __float2bfloat16(v);
        g_B2h[i] = hi;
        g_B2l[i] = __float2bfloat16(v - __bfloat162float(hi));
    }
}

// sconv over k in [K0,K0+KN): one thread, one row m; Y stored [k][m] (coalesced)
template <int K0, int KN, int CIN, int XSTR, int MODE_IN>
__device__ __forceinline__ void sconv_seg(const float* __restrict__ xb,
                                          const float* __restrict__ wb,
                                          __nv_bfloat16* __restrict__ yh,
                                          __nv_bfloat16* __restrict__ yl,
                                          int m) {
    constexpr size_t KS = (size_t)NB_TOTAL * CIN;
    float acc[KN];
#pragma unroll
    for (int kk = 0; kk < KN; kk++) acc[kk] = 0.f;
#pragma unroll 1
    for (int cb = 0; cb < CIN; cb += 4) {
        float wv[4][5];
#pragma unroll
        for (int cc = 0; cc < 4; cc++)
#pragma unroll
            for (int g = 0; g < 5; g++) wv[cc][g] = wb[(cb + cc) * 5 + g];
#pragma unroll
        for (int kk = 0; kk < KN; kk++) {
            float4 xv;
            if constexpr (MODE_IN == 0)
                xv = *reinterpret_cast<const float4*>(xb + (K0 + kk) * XSTR + cb);
            else
                xv = __ldg(reinterpret_cast<const float4*>(
                        xb + (size_t)(K0 + kk) * KS + cb));
            const int g = ggrp(K0 + kk);
            acc[kk] = fmaf(xv.x, wv[0][g], acc[kk]);
            acc[kk] = fmaf(xv.y, wv[1][g], acc[kk]);
            acc[kk] = fmaf(xv.z, wv[2][g], acc[kk]);
            acc[kk] = fmaf(xv.w, wv[3][g], acc[kk]);
        }
    }
#pragma unroll
    for (int kk = 0; kk < KN; kk++) {
        const float v = acc[kk] * scl_of(K0 + kk);
        const __nv_bfloat16 h = __float2bfloat16(v);
        yh[(K0 + kk) * MSTR + m] = h;
        yl[(K0 + kk) * MSTR + m] = __float2bfloat16(v - __bfloat162float(h));
    }
}

// ---------------- per-layer persistent kernel -------------------------------
template <int CIN, int COUT, int MODE_IN, int MODE_OUT>
__global__ void __launch_bounds__(NTT, 1)
scnn_layer(const float* __restrict__ in, const float* __restrict__ w,
           float* __restrict__ out, int ntiles) {
    constexpr int TB   = MTILE / COUT;
    constexpr int MIN_ = TB * CIN;
    constexpr int XSTR = MIN_ + 4;
    constexpr int WSTR = CIN * 5 + 1;
    constexpr int OFF_W_ = OFF_W;
    constexpr int OFF_X_ = OFF_W_ + COUT * WSTR * 4;
    static_assert(MTILE % COUT == 0 && CIN % 4 == 0, "cfg");

    extern __shared__ char smc[];
    const uint32_t sb = smem_u32(smc);
    const int tid = threadIdx.x, wid = tid >> 5, lane = tid & 31;

    __nv_bfloat16* Yh = (__nv_bfloat16*)(smc + OFF_YH);
    __nv_bfloat16* Yl = (__nv_bfloat16*)(smc + OFF_YL);
    float* s_exg = (float*)(smc + OFF_EXG);
    float* s_w = (float*)(smc + OFF_W_);
    float* s_x = (float*)(smc + OFF_X_);

    // ---- one-time setup: zero Y (covers k-pads 45..47), copy B, load W -----
    for (int i = tid; i < (OFF_EXG - OFF_YH) / 4; i += NTT)
        ((uint32_t*)(smc + OFF_YH))[i] = 0;
    {
        const uint32_t* s1h = (const uint32_t*)g_B1h;
        const uint32_t* s1l = (const uint32_t*)g_B1l;
        uint32_t* d1h = (uint32_t*)(smc + OFF_B1H);
        uint32_t* d1l = (uint32_t*)(smc + OFF_B1L);
        for (int i = tid; i < 96 * 24; i += NTT) {
            int n = i / 24, kk = i - n * 24;
            d1h[(n * B1STR) / 2 + kk] = s1h[i];
            d1l[(n * B1STR) / 2 + kk] = s1l[i];
        }
        const uint32_t* s2h = (const uint32_t*)g_B2h;
        const uint32_t* s2l = (const uint32_t*)g_B2l;
        uint32_t* d2h = (uint32_t*)(smc + OFF_B2H);
        uint32_t* d2l = (uint32_t*)(smc + OFF_B2L);
        for (int i = tid; i < 48 * 48; i += NTT) {
            int n = i / 48, kk = i - n * 48;
            d2h[(n * B2STR) / 2 + kk] = s2h[i];
            d2l[(n * B2STR) / 2 + kk] = s2l[i];
        }
    }
    for (int i = tid; i < COUT * CIN * 5; i += NTT) {
        int o = i / (CIN * 5);
        s_w[o * WSTR + (i - o * (CIN * 5))] = w[i];
    }

    // ---- loop-invariant addressing -----------------------------------------
    const int pairid = wid >> 1, nh = wid & 1;
    const int mb = pairid * 32;                 // warp m-base (32 rows)
    const int g = lane >> 3, rr = lane & 7;
    const int qr = lane >> 2, qc = lane & 3;
    const int bar_id = 1 + pairid;

    // A (Y) trans loads: Y is [k][m]; matrix j -> (m-half = j&1, k-half = j>>1)
    uint32_t aYt[2];
#pragma unroll
    for (int mt = 0; mt < 2; mt++)
        aYt[mt] = sb + OFF_YH +
            (((g >> 1) * 8 + rr) * MSTR + mb + mt * 16 + (g & 1) * 8) * 2;
    const uint32_t bB1 = sb + OFF_B1H +
        ((nh * 48 + (g >> 1) * 8 + rr) * B1STR + (g & 1) * 8) * 2;
    const uint32_t bB2 = sb + OFF_B2H +
        (((g >> 1) * 8 + rr) * B2STR + nh * 48 + (g & 1) * 8) * 2;

    // sconv mapping: warps 0-5 kseg0 rows (w%6)*32, warps 6-11 kseg1
    const int rS = (wid % 6) * 32 + lane;
    const int segS = wid / 6;
    const int tS = rS / COUT, oS = rS % COUT;
    const float* wbS = s_w + oS * WSTR;

    // ---- L1 only: stage first tile's x (guarded) ---------------------------
    int t = blockIdx.x;
    if constexpr (MODE_IN == 0) {
        if (t < ntiles) {
            const size_t bi = (size_t)t * (MIN_ * NC);
            for (int i = tid; i < MIN_ * NC; i += NTT) {
                int m = i / NC, k = i - m * NC;
                int b = t * TB + m / CIN;
                s_x[k * XSTR + m] = (b < NB_TOTAL) ? in[bi + i] : 0.f;
            }
        }
    }
    __syncthreads();

    // ---- persistent tile loop ----------------------------------------------
    for (; t < ntiles; t += gridDim.x) {
        // phase A: sconv -> Y[k][m]
        {
            const float* xb;
            if constexpr (MODE_IN == 0) {
                xb = s_x + tS * CIN;
            } else {
                int b = t * TB + tS;
                if (b >= NB_TOTAL) b = NB_TOTAL - 1;
                xb = in + (size_t)b * CIN;
            }
            if (segS == 0)
                sconv_seg< 0, 22, CIN, XSTR, MODE_IN>(xb, wbS, Yh, Yl, rS);
            else
                sconv_seg<22, 23, CIN, XSTR, MODE_IN>(xb, wbS, Yh, Yl, rS);
        }
        __syncthreads();

        // phase B: GEMM1 (m32 x n-half48), c1 in registers
        float c1[2][6][4];
#pragma unroll
        for (int a = 0; a < 2; a++)
#pragma unroll
            for (int i = 0; i < 6; i++)
#pragma unroll
                for (int j = 0; j < 4; j++) c1[a][i][j] = 0.f;

#pragma unroll
        for (int ks = 0; ks < 3; ks++) {
            uint32_t ah[2][4], al[2][4];
#pragma unroll
            for (int mt = 0; mt < 2; mt++) {
                ldsm_x4t(ah[mt], aYt[mt] + ks * (16 * MSTR * 2));
                ldsm_x4t(al[mt], aYt[mt] + ks * (16 * MSTR * 2) + DYL);
            }
#pragma unroll
            for (int np = 0; np < 3; np++) {
                const uint32_t bo = bB1 + ks * 32 + np * (16 * B1STR * 2);
                uint32_t bh[4], bl[4];
                ldsm_x4(bh, bo);
                ldsm_x4(bl, bo + DB1);
#pragma unroll
                for (int mt = 0; mt < 2; mt++) {
                    mma_bf16(c1[mt][2 * np], ah[mt], bh[0], bh[1]);
                    mma_bf16(c1[mt][2 * np], ah[mt], bl[0], bl[1]);
                    mma_bf16(c1[mt][2 * np], al[mt], bh[0], bh[1]);
                    mma_bf16(c1[mt][2 * np + 1], ah[mt], bh[2], bh[3]);
                    mma_bf16(c1[mt][2 * np + 1], ah[mt], bl[2], bl[3]);
                    mma_bf16(c1[mt][2 * np + 1], al[mt], bh[2], bh[3]);
                }
            }
        }

        // L1 only: prefetch next tile's x (x dead after sconv)
        if constexpr (MODE_IN == 0) {
            const int tn = t + gridDim.x;
            if (tn < ntiles) {
                const size_t bi = (size_t)tn * (MIN_ * NC);
                for (int i = tid; i < MIN_ * NC; i += NTT) {
                    int m = i / NC, k = i - m * NC;
                    int b = tn * TB + m / CIN;
                    s_x[k * XSTR + m] = (b < NB_TOTAL) ? in[bi + i] : 0.f;
                }
            }
        }

        // phase C: GEMM2 partial (K = this warp's p-half), register repack
        float c2[2][6][4];
#pragma unroll
        for (int a = 0; a < 2; a++)
#pragma unroll
            for (int i = 0; i < 6; i++)
#pragma unroll
                for (int j = 0; j < 4; j++) c2[a][i][j] = 0.f;

#pragma unroll
        for (int kc = 0; kc < 3; kc++) {
            uint32_t a2h[2][4], a2l[2][4];
#pragma unroll
            for (int mt = 0; mt < 2; mt++)
#pragma unroll
                for (int u = 0; u < 2; u++)
#pragma unroll
                    for (int v = 0; v < 2; v++) {
                        const float p0 = fmaxf(c1[mt][2 * kc + u][2 * v], 0.f);
                        const float p1 = fmaxf(c1[mt][2 * kc + u][2 * v + 1], 0.f);
                        const __nv_bfloat16 h0 = __float2bfloat16(p0);
                        const __nv_bfloat16 h1 = __float2bfloat16(p1);
                        a2h[mt][2 * u + v] = pack2bf(h0, h1);
                        a2l[mt][2 * u + v] =
                            pack2bf(__float2bfloat16(p0 - __bfloat162float(h0)),
                                    __float2bfloat16(p1 - __bfloat162float(h1)));
                    }
#pragma unroll
            for (int np = 0; np < 3; np++) {
                const uint32_t bo = bB2 + kc * 32 + np * (16 * B2STR * 2);
                uint32_t bh[4], bl[4];
                ldsm_x4(bh, bo);
                ldsm_x4(bl, bo + DB2);
#pragma unroll
                for (int mt = 0; mt < 2; mt++) {
                    mma_bf16(c2[mt][2 * np], a2h[mt], bh[0], bh[1]);
                    mma_bf16(c2[mt][2 * np], a2h[mt], bl[0], bl[1]);
                    mma_bf16(c2[mt][2 * np], a2l[mt], bh[0], bh[1]);
                    mma_bf16(c2[mt][2 * np + 1], a2h[mt], bh[2], bh[3]);
                    mma_bf16(c2[mt][2 * np + 1], a2h[mt], bl[2], bl[3]);
                    mma_bf16(c2[mt][2 * np + 1], a2l[mt], bh[2], bh[3]);
                }
            }
        }

        // phase D: pair exchange (odd warp writes partials, even accumulates)
        if (nh == 1) {
#pragma unroll
            for (int mt = 0; mt < 2; mt++)
#pragma unroll
                for (int j = 0; j < 6; j++)
#pragma unroll
                    for (int h = 0; h < 2; h++) {
                        const int row = mb + mt * 16 + qr + 8 * h;
                        const int col = 8 * j + 2 * qc;
                        s_exg[row * EXGSTR + col]     = c2[mt][j][2 * h];
                        s_exg[row * EXGSTR + col + 1] = c2[mt][j][2 * h + 1];
                    }
        }
        asm volatile("bar.sync %0, %1;" :: "r"(bar_id), "r"(64) : "memory");
        if (nh == 0) {
#pragma unroll
            for (int mt = 0; mt < 2; mt++)
#pragma unroll
                for (int j = 0; j < 6; j++)
#pragma unroll
                    for (int h = 0; h < 2; h++) {
                        const int row = mb + mt * 16 + qr + 8 * h;
                        const int col = 8 * j + 2 * qc;
                        const float v0 =
                            c2[mt][j][2 * h] + s_exg[row * EXGSTR + col];
                        const float v1 =
                            c2[mt][j][2 * h + 1] + s_exg[row * EXGSTR + col + 1];
                        if constexpr (MODE_OUT == 1) {      // [k][b][ch]
                            const int b = t * TB + row / COUT;
                            const int ch = row % COUT;
                            if (b < NB_TOTAL) {
                                if (col < NC)
                                    out[((size_t)col * NB_TOTAL + b) * COUT + ch] = v0;
                                if (col + 1 < NC)
                                    out[((size_t)(col + 1) * NB_TOTAL + b) * COUT + ch] = v1;
                            }
                        } else {                            // [b][ch][k] (L6)
                            if (t * TB + row / COUT < NB_TOTAL) {
                                const size_t ro = ((size_t)t * MTILE + row) * NC;
                                if (col < NC)     out[ro + col]     = v0;
                                if (col + 1 < NC) out[ro + col + 1] = v1;
                            }
                        }
                    }
        }
        __syncthreads();   // protect Y + exchange region before next tile
    }
}

// ---------------- host ------------------------------------------------------
extern "C" void kernel_launch(void* const* d_in, const int* in_sizes, int n_in,
                              void* d_out, int out_size) {
    (void)in_sizes; (void)n_in; (void)out_size;

    const float* x    = (const float*)d_in[0];
    const float* sft  = (const float*)d_in[1];
    const float* isft = (const float*)d_in[2];
    const float* w1   = (const float*)d_in[3];
    const float* w2   = (const float*)d_in[4];
    const float* w3   = (const float*)d_in[5];
    const float* w4   = (const float*)d_in[6];
    const float* w5   = (const float*)d_in[7];
    const float* w6   = (const float*)d_in[8];
    float* out = (float*)d_out;

    float *bufA = nullptr, *bufB = nullptr;
    cudaGetSymbolAddress((void**)&bufA, g_bufA);
    cudaGetSymbolAddress((void**)&bufB, g_bufB);

    cudaFuncSetAttribute((const void*)scnn_layer<4, 16, 0, 1>,
        cudaFuncAttributeMaxDynamicSharedMemorySize, smem_total_c(4, 16, 0));
    cudaFuncSetAttribute((const void*)scnn_layer<16, 32, 1, 1>,
        cudaFuncAttributeMaxDynamicSharedMemorySize, smem_total_c(16, 32, 1));
    cudaFuncSetAttribute((const void*)scnn_layer<32, 64, 1, 1>,
        cudaFuncAttributeMaxDynamicSharedMemorySize, smem_total_c(32, 64, 1));
    cudaFuncSetAttribute((const void*)scnn_layer<64, 32, 1, 1>,
        cudaFuncAttributeMaxDynamicSharedMemorySize, smem_total_c(64, 32, 1));
    cudaFuncSetAttribute((const void*)scnn_layer<32, 16, 1, 1>,
        cudaFuncAttributeMaxDynamicSharedMemorySize, smem_total_c(32, 16, 1));
    cudaFuncSetAttribute((const void*)scnn_layer<16, 4, 1, 0>,
        cudaFuncAttributeMaxDynamicSharedMemorySize, smem_total_c(16, 4, 1));

    build_B<<<1, 256>>>(sft, isft);

    // tiles = ceil(NB / TB), TB = 192/COUT
    scnn_layer<4, 16, 0, 1><<<148, NTT, smem_total_c(4, 16, 0)>>>(
        x, w1, bufA, (NB_TOTAL + 11) / 12);
    scnn_layer<16, 32, 1, 1><<<148, NTT, smem_total_c(16, 32, 1)>>>(
        bufA, w2, bufB, (NB_TOTAL + 5) / 6);
    scnn_layer<32, 64, 1, 1><<<148, NTT, smem_total_c(32, 64, 1)>>>(
        bufB, w3, bufA, (NB_TOTAL + 2) / 3);
    scnn_layer<64, 32, 1, 1><<<148, NTT, smem_total_c(64, 32, 1)>>>(
        bufA, w4, bufB, (NB_TOTAL + 5) / 6);
    scnn_layer<32, 16, 1, 1><<<148, NTT, smem_total_c(32, 16, 1)>>>(
        bufB, w5, bufA, (NB_TOTAL + 11) / 12);
    scnn_layer<16, 4, 1, 0><<<148, NTT, smem_total_c(16, 4, 1)>>>(
        bufA, w6, out, (NB_TOTAL + 47) / 48);
}

// round 12
// speedup vs baseline: 1.0412x; 1.0412x over previous
#include <cuda_runtime.h>
#include <cuda_bf16.h>
#include <cstdint>
#include <cstddef>

// ----------------------------------------------------------------------------
// SCNN via warp-level HMMA (mma.sync bf16, fp32 accum), persistent CTAs.
// R11: each warp owns m32 x FULL N for both GEMMs (B-fragments amortized over
// 2 m-tiles, register-fused GEMM1->GEMM2, NO partial exchange). 10 warps,
// M-tile = 320 rows, 1 CTA/SM. Y transposed [k][m]: coalesced sconv stores,
// ldmatrix.trans A-loads. 2 barriers/tile. All layer tile counts divide 50000.
// ----------------------------------------------------------------------------

#define NB_TOTAL 50000
#define NC 45
#define ND 90
#define NTT 320
#define MTILE 320
#define MSTR 328     // Y [k][m] row length (320 + 8 pad); 656B rows, gcd4 banks
#define B1STR  56    // B1 [n=96][k=48], 112B rows
#define B2STR 104    // B2 [n=48][k=96], 208B rows

__device__ float g_bufA[(size_t)NB_TOTAL * 64 * NC];
__device__ float g_bufB[(size_t)NB_TOTAL * 32 * NC];
__device__ __nv_bfloat16 g_B1h[96 * 48], g_B1l[96 * 48];
__device__ __nv_bfloat16 g_B2h[48 * 96], g_B2l[48 * 96];

// ---------------- smem layout (bytes) ---------------------------------------
#define OFF_B1H 0
#define OFF_B1L 10752
#define OFF_B2H 21504
#define OFF_B2L 31488
#define OFF_YH  41472          /* 48*328*2 = 31488 */
#define OFF_YL  72960
#define OFF_W   104448
#define DB1 10752
#define DB2  9984
#define DYL 31488

__host__ __device__ constexpr int smem_total_c(int CIN, int COUT, int MODE_IN) {
    return OFF_W + COUT * (CIN * 5 + 1) * 4 +
           (MODE_IN == 0 ? NC * ((MTILE / COUT) * CIN + 4) * 4 : 0);
}

// ---------------- PTX helpers ----------------------------------------------
__device__ __forceinline__ uint32_t smem_u32(const void* p) {
    uint32_t a;
    asm("{ .reg .u64 t; cvta.to.shared.u64 t, %1; cvt.u32.u64 %0, t; }"
        : "=r"(a) : "l"(p));
    return a;
}
__device__ __forceinline__ void ldsm_x4(uint32_t* r, uint32_t addr) {
    asm volatile("ldmatrix.sync.aligned.m8n8.x4.shared.b16 {%0,%1,%2,%3}, [%4];"
                 : "=r"(r[0]), "=r"(r[1]), "=r"(r[2]), "=r"(r[3]) : "r"(addr));
}
__device__ __forceinline__ void ldsm_x4t(uint32_t* r, uint32_t addr) {
    asm volatile("ldmatrix.sync.aligned.m8n8.x4.trans.shared.b16 {%0,%1,%2,%3}, [%4];"
                 : "=r"(r[0]), "=r"(r[1]), "=r"(r[2]), "=r"(r[3]) : "r"(addr));
}
__device__ __forceinline__ void mma_bf16(float* c, const uint32_t* a,
                                         uint32_t b0, uint32_t b1) {
    asm volatile(
        "mma.sync.aligned.m16n8k16.row.col.f32.bf16.bf16.f32 "
        "{%0,%1,%2,%3}, {%4,%5,%6,%7}, {%8,%9}, {%0,%1,%2,%3};"
        : "+f"(c[0]), "+f"(c[1]), "+f"(c[2]), "+f"(c[3])
        : "r"(a[0]), "r"(a[1]), "r"(a[2]), "r"(a[3]), "r"(b0), "r"(b1));
}
__device__ __forceinline__ uint32_t pack2bf(__nv_bfloat16 a, __nv_bfloat16 b) {
    return (uint32_t)__bfloat16_as_ushort(a) |
           ((uint32_t)__bfloat16_as_ushort(b) << 16);
}

// ---------------- problem constants -----------------------------------------
__host__ __device__ __forceinline__ constexpr int ggrp(int k) {
    return (k < 1) ? 0 : (k < 6) ? 1 : (k < 15) ? 2 : (k < 28) ? 3 : 4;
}
__device__ __forceinline__ float scl_of(int k) {
    const int g = ggrp(k);
    return g == 0 ? 1.77245385090552f
         : g == 1 ? 0.79266545952121f
         : g == 2 ? 0.59081795030184f
         : g == 3 ? 0.49159027f
         :          0.42988321f;
}

// ---------------- setup: pre-split B matrices to bf16 hi/lo -----------------
__global__ void build_B(const float* __restrict__ sft,
                        const float* __restrict__ isft) {
    const int tid = threadIdx.x;
    for (int i = tid; i < 96 * 48; i += 256) {     // B1[n=p(96)][k(48)]
        int n = i / 48, k = i - n * 48;
        float v = (n < ND && k < NC) ? isft[n * NC + k] : 0.f;
        __nv_bfloat16 hi = __float2bfloat16(v);
        g_B1h[i] = hi;
        g_B1l[i] = __float2bfloat16(v - __bfloat162float(hi));
    }
    for (int i = tid; i < 48 * 96; i += 256) {     // B2[n=k(48)][k=p(96)]
        int n = i / 96, p = i - n * 96;
        float v = (n < NC && p < ND) ? sft[n * ND + p] : 0.f;
        __nv_bfloat16 hi = __float2bfloat16(v);
        g_B2h[i] = hi;
        g_B2l[i] = __float2bfloat16(v - __bfloat162float(hi));
    }
}

// sconv: one thread, one row m, all 45 k; Y stored [k][m] (coalesced 2B stores)
template <int CIN, int XSTR, int MODE_IN>
__device__ __forceinline__ void sconv_row(const float* __restrict__ xb,
                                          const float* __restrict__ wb,
                                          __nv_bfloat16* __restrict__ yh,
                                          __nv_bfloat16* __restrict__ yl,
                                          int m) {
    constexpr size_t KS = (size_t)NB_TOTAL * CIN;
    float acc[NC];
#pragma unroll
    for (int k = 0; k < NC; k++) acc[k] = 0.f;
#pragma unroll 1
    for (int cb = 0; cb < CIN; cb += 4) {
        float wv[4][5];
#pragma unroll
        for (int cc = 0; cc < 4; cc++)
#pragma unroll
            for (int g = 0; g < 5; g++) wv[cc][g] = wb[(cb + cc) * 5 + g];
#pragma unroll
        for (int k = 0; k < NC; k++) {
            float4 xv;
            if constexpr (MODE_IN == 0)
                xv = *reinterpret_cast<const float4*>(xb + k * XSTR + cb);
            else
                xv = __ldg(reinterpret_cast<const float4*>(
                        xb + (size_t)k * KS + cb));
            const int g = ggrp(k);
            acc[k] = fmaf(xv.x, wv[0][g], acc[k]);
            acc[k] = fmaf(xv.y, wv[1][g], acc[k]);
            acc[k] = fmaf(xv.z, wv[2][g], acc[k]);
            acc[k] = fmaf(xv.w, wv[3][g], acc[k]);
        }
    }
#pragma unroll
    for (int k = 0; k < NC; k++) {
        const float v = acc[k] * scl_of(k);
        const __nv_bfloat16 h = __float2bfloat16(v);
        yh[k * MSTR + m] = h;
        yl[k * MSTR + m] = __float2bfloat16(v - __bfloat162float(h));
    }
}

// ---------------- per-layer persistent kernel -------------------------------
template <int CIN, int COUT, int MODE_IN, int MODE_OUT>
__global__ void __launch_bounds__(NTT, 1)
scnn_layer(const float* __restrict__ in, const float* __restrict__ w,
           float* __restrict__ out, int ntiles) {
    constexpr int TB   = MTILE / COUT;
    constexpr int MIN_ = TB * CIN;
    constexpr int XSTR = MIN_ + 4;
    constexpr int WSTR = CIN * 5 + 1;
    constexpr int OFF_X_ = OFF_W + COUT * WSTR * 4;
    static_assert(MTILE % COUT == 0 && CIN % 4 == 0, "cfg");

    extern __shared__ char smc[];
    const uint32_t sb = smem_u32(smc);
    const int tid = threadIdx.x, wid = tid >> 5, lane = tid & 31;

    __nv_bfloat16* Yh = (__nv_bfloat16*)(smc + OFF_YH);
    __nv_bfloat16* Yl = (__nv_bfloat16*)(smc + OFF_YL);
    float* s_w = (float*)(smc + OFF_W);
    float* s_x = (float*)(smc + OFF_X_);

    // ---- one-time setup: zero Y (covers k-pads 45..47), copy B, load W -----
    for (int i = tid; i < (OFF_W - OFF_YH) / 4; i += NTT)
        ((uint32_t*)(smc + OFF_YH))[i] = 0;
    {
        const uint32_t* s1h = (const uint32_t*)g_B1h;
        const uint32_t* s1l = (const uint32_t*)g_B1l;
        uint32_t* d1h = (uint32_t*)(smc + OFF_B1H);
        uint32_t* d1l = (uint32_t*)(smc + OFF_B1L);
        for (int i = tid; i < 96 * 24; i += NTT) {
            int n = i / 24, kk = i - n * 24;
            d1h[(n * B1STR) / 2 + kk] = s1h[i];
            d1l[(n * B1STR) / 2 + kk] = s1l[i];
        }
        const uint32_t* s2h = (const uint32_t*)g_B2h;
        const uint32_t* s2l = (const uint32_t*)g_B2l;
        uint32_t* d2h = (uint32_t*)(smc + OFF_B2H);
        uint32_t* d2l = (uint32_t*)(smc + OFF_B2L);
        for (int i = tid; i < 48 * 48; i += NTT) {
            int n = i / 48, kk = i - n * 48;
            d2h[(n * B2STR) / 2 + kk] = s2h[i];
            d2l[(n * B2STR) / 2 + kk] = s2l[i];
        }
    }
    for (int i = tid; i < COUT * CIN * 5; i += NTT) {
        int o = i / (CIN * 5);
        s_w[o * WSTR + (i - o * (CIN * 5))] = w[i];
    }

    // ---- loop-invariant addressing -----------------------------------------
    const int mb = wid * 32;                    // warp m-base (32 rows)
    const int g = lane >> 3, rr = lane & 7;
    const int qr = lane >> 2, qc = lane & 3;

    // A (Y) trans loads: Y is [k][m]; matrix j -> (m-half = j&1, k-half = j>>1)
    uint32_t aYt[2];
#pragma unroll
    for (int mt = 0; mt < 2; mt++)
        aYt[mt] = sb + OFF_YH +
            (((g >> 1) * 8 + rr) * MSTR + mb + mt * 16 + (g & 1) * 8) * 2;
    const uint32_t bB1 = sb + OFF_B1H +
        (((g >> 1) * 8 + rr) * B1STR + (g & 1) * 8) * 2;
    const uint32_t bB2 = sb + OFF_B2H +
        (((g >> 1) * 8 + rr) * B2STR + (g & 1) * 8) * 2;

    // sconv mapping: one thread per row
    const int rS = tid;
    const int tS = rS / COUT, oS = rS % COUT;
    const float* wbS = s_w + oS * WSTR;

    // ---- L1 only: stage first tile's x (guarded) ---------------------------
    int t = blockIdx.x;
    if constexpr (MODE_IN == 0) {
        if (t < ntiles) {
            const size_t bi = (size_t)t * (MIN_ * NC);
            for (int i = tid; i < MIN_ * NC; i += NTT) {
                int m = i / NC, k = i - m * NC;
                int b = t * TB + m / CIN;
                s_x[k * XSTR + m] = (b < NB_TOTAL) ? in[bi + i] : 0.f;
            }
        }
    }
    __syncthreads();

    // ---- persistent tile loop ----------------------------------------------
    for (; t < ntiles; t += gridDim.x) {
        // phase A: sconv -> Y[k][m]
        {
            const float* xb;
            if constexpr (MODE_IN == 0) {
                xb = s_x + tS * CIN;
            } else {
                int b = t * TB + tS;
                if (b >= NB_TOTAL) b = NB_TOTAL - 1;
                xb = in + (size_t)b * CIN;
            }
            sconv_row<CIN, XSTR, MODE_IN>(xb, wbS, Yh, Yl, rS);
        }
        __syncthreads();

        // phase B: GEMM1 (m32 x full N=96), c1 in registers
        float c1[2][12][4];
#pragma unroll
        for (int a = 0; a < 2; a++)
#pragma unroll
            for (int i = 0; i < 12; i++)
#pragma unroll
                for (int j = 0; j < 4; j++) c1[a][i][j] = 0.f;

#pragma unroll
        for (int ks = 0; ks < 3; ks++) {
            uint32_t ah[2][4], al[2][4];
#pragma unroll
            for (int mt = 0; mt < 2; mt++) {
                ldsm_x4t(ah[mt], aYt[mt] + ks * (16 * MSTR * 2));
                ldsm_x4t(al[mt], aYt[mt] + ks * (16 * MSTR * 2) + DYL);
            }
#pragma unroll
            for (int np = 0; np < 6; np++) {
                const uint32_t bo = bB1 + ks * 32 + np * (16 * B1STR * 2);
                uint32_t bh[4], bl[4];
                ldsm_x4(bh, bo);
                ldsm_x4(bl, bo + DB1);
#pragma unroll
                for (int mt = 0; mt < 2; mt++) {
                    mma_bf16(c1[mt][2 * np], ah[mt], bh[0], bh[1]);
                    mma_bf16(c1[mt][2 * np], ah[mt], bl[0], bl[1]);
                    mma_bf16(c1[mt][2 * np], al[mt], bh[0], bh[1]);
                    mma_bf16(c1[mt][2 * np + 1], ah[mt], bh[2], bh[3]);
                    mma_bf16(c1[mt][2 * np + 1], ah[mt], bl[2], bl[3]);
                    mma_bf16(c1[mt][2 * np + 1], al[mt], bh[2], bh[3]);
                }
            }
        }

        // L1 only: prefetch next tile's x (x dead after sconv)
        if constexpr (MODE_IN == 0) {
            const int tn = t + gridDim.x;
            if (tn < ntiles) {
                const size_t bi = (size_t)tn * (MIN_ * NC);
                for (int i = tid; i < MIN_ * NC; i += NTT) {
                    int m = i / NC, k = i - m * NC;
                    int b = tn * TB + m / CIN;
                    s_x[k * XSTR + m] = (b < NB_TOTAL) ? in[bi + i] : 0.f;
                }
            }
        }

        // phase C: GEMM2 (m32 x full N=48, full K), register repack from c1
        float c2[2][6][4];
#pragma unroll
        for (int a = 0; a < 2; a++)
#pragma unroll
            for (int i = 0; i < 6; i++)
#pragma unroll
                for (int j = 0; j < 4; j++) c2[a][i][j] = 0.f;

#pragma unroll
        for (int kc = 0; kc < 6; kc++) {
            uint32_t a2h[2][4], a2l[2][4];
#pragma unroll
            for (int mt = 0; mt < 2; mt++)
#pragma unroll
                for (int u = 0; u < 2; u++)
#pragma unroll
                    for (int v = 0; v < 2; v++) {
                        const float p0 = fmaxf(c1[mt][2 * kc + u][2 * v], 0.f);
                        const float p1 = fmaxf(c1[mt][2 * kc + u][2 * v + 1], 0.f);
                        const __nv_bfloat16 h0 = __float2bfloat16(p0);
                        const __nv_bfloat16 h1 = __float2bfloat16(p1);
                        a2h[mt][2 * u + v] = pack2bf(h0, h1);
                        a2l[mt][2 * u + v] =
                            pack2bf(__float2bfloat16(p0 - __bfloat162float(h0)),
                                    __float2bfloat16(p1 - __bfloat162float(h1)));
                    }
#pragma unroll
            for (int np = 0; np < 3; np++) {
                const uint32_t bo = bB2 + kc * 32 + np * (16 * B2STR * 2);
                uint32_t bh[4], bl[4];
                ldsm_x4(bh, bo);
                ldsm_x4(bl, bo + DB2);
#pragma unroll
                for (int mt = 0; mt < 2; mt++) {
                    mma_bf16(c2[mt][2 * np], a2h[mt], bh[0], bh[1]);
                    mma_bf16(c2[mt][2 * np], a2h[mt], bl[0], bl[1]);
                    mma_bf16(c2[mt][2 * np], a2l[mt], bh[0], bh[1]);
                    mma_bf16(c2[mt][2 * np + 1], a2h[mt], bh[2], bh[3]);
                    mma_bf16(c2[mt][2 * np + 1], a2h[mt], bl[2], bl[3]);
                    mma_bf16(c2[mt][2 * np + 1], a2l[mt], bh[2], bh[3]);
                }
            }
        }

        // phase D: store c2 straight to gmem (guarded)
#pragma unroll
        for (int mt = 0; mt < 2; mt++)
#pragma unroll
            for (int j = 0; j < 6; j++) {
                const int col = 8 * j + 2 * qc;
#pragma unroll
                for (int h = 0; h < 2; h++) {
                    const int row = mb + mt * 16 + qr + 8 * h;
                    const float v0 = c2[mt][j][2 * h];
                    const float v1 = c2[mt][j][2 * h + 1];
                    if constexpr (MODE_OUT == 1) {       // [k][b][ch]
                        const int b = t * TB + row / COUT;
                        const int ch = row % COUT;
                        if (b < NB_TOTAL) {
                            if (col < NC)
                                out[((size_t)col * NB_TOTAL + b) * COUT + ch] = v0;
                            if (col + 1 < NC)
                                out[((size_t)(col + 1) * NB_TOTAL + b) * COUT + ch] = v1;
                        }
                    } else {                             // [b][ch][k] (L6)
                        if (t * TB + row / COUT < NB_TOTAL) {
                            const size_t ro = ((size_t)t * MTILE + row) * NC;
                            if (col < NC)     out[ro + col]     = v0;
                            if (col + 1 < NC) out[ro + col + 1] = v1;
                        }
                    }
                }
            }
        __syncthreads();   // protect Y before next tile's sconv
    }
}

// ---------------- host ------------------------------------------------------
extern "C" void kernel_launch(void* const* d_in, const int* in_sizes, int n_in,
                              void* d_out, int out_size) {
    (void)in_sizes; (void)n_in; (void)out_size;

    const float* x    = (const float*)d_in[0];
    const float* sft  = (const float*)d_in[1];
    const float* isft = (const float*)d_in[2];
    const float* w1   = (const float*)d_in[3];
    const float* w2   = (const float*)d_in[4];
    const float* w3   = (const float*)d_in[5];
    const float* w4   = (const float*)d_in[6];
    const float* w5   = (const float*)d_in[7];
    const float* w6   = (const float*)d_in[8];
    float* out = (float*)d_out;

    float *bufA = nullptr, *bufB = nullptr;
    cudaGetSymbolAddress((void**)&bufA, g_bufA);
    cudaGetSymbolAddress((void**)&bufB, g_bufB);

    cudaFuncSetAttribute((const void*)scnn_layer<4, 16, 0, 1>,
        cudaFuncAttributeMaxDynamicSharedMemorySize, smem_total_c(4, 16, 0));
    cudaFuncSetAttribute((const void*)scnn_layer<16, 32, 1, 1>,
        cudaFuncAttributeMaxDynamicSharedMemorySize, smem_total_c(16, 32, 1));
    cudaFuncSetAttribute((const void*)scnn_layer<32, 64, 1, 1>,
        cudaFuncAttributeMaxDynamicSharedMemorySize, smem_total_c(32, 64, 1));
    cudaFuncSetAttribute((const void*)scnn_layer<64, 32, 1, 1>,
        cudaFuncAttributeMaxDynamicSharedMemorySize, smem_total_c(64, 32, 1));
    cudaFuncSetAttribute((const void*)scnn_layer<32, 16, 1, 1>,
        cudaFuncAttributeMaxDynamicSharedMemorySize, smem_total_c(32, 16, 1));
    cudaFuncSetAttribute((const void*)scnn_layer<16, 4, 1, 0>,
        cudaFuncAttributeMaxDynamicSharedMemorySize, smem_total_c(16, 4, 1));

    build_B<<<1, 256>>>(sft, isft);

    // tiles = NB / TB (all exact): TB = 320/COUT
    scnn_layer<4, 16, 0, 1><<<148, NTT, smem_total_c(4, 16, 0)>>>(
        x, w1, bufA, NB_TOTAL / 20);
    scnn_layer<16, 32, 1, 1><<<148, NTT, smem_total_c(16, 32, 1)>>>(
        bufA, w2, bufB, NB_TOTAL / 10);
    scnn_layer<32, 64, 1, 1><<<148, NTT, smem_total_c(32, 64, 1)>>>(
        bufB, w3, bufA, NB_TOTAL / 5);
    scnn_layer<64, 32, 1, 1><<<148, NTT, smem_total_c(64, 32, 1)>>>(
        bufA, w4, bufB, NB_TOTAL / 10);
    scnn_layer<32, 16, 1, 1><<<148, NTT, smem_total_c(32, 16, 1)>>>(
        bufB, w5, bufA, NB_TOTAL / 20);
    scnn_layer<16, 4, 1, 0><<<148, NTT, smem_total_c(16, 4, 1)>>>(
        bufA, w6, out, NB_TOTAL / 80);
}

// round 13
// speedup vs baseline: 1.1796x; 1.1329x over previous
#include <cuda_runtime.h>
#include <cuda_bf16.h>
#include <cstdint>
#include <cstddef>

// ----------------------------------------------------------------------------
// SCNN via warp-level HMMA (mma.sync bf16, fp32 accum), persistent CTAs.
// R12: R8 per-warp design (m16 x full-N, register-fused GEMM1->GEMM2) at
// M=128 / 256 threads / 2 CTAs per SM (independent barrier domains), plus
// R11's transposed Y [k][m] (coalesced sconv stores, ldmatrix.trans loads).
// W in smem; x read from gmem in [k][b][c] layout (broadcast float4).
// ----------------------------------------------------------------------------

#define NB_TOTAL 50000
#define NC 45
#define ND 90
#define NTT 256
#define MTILE 128
#define MSTR 136     // Y [k][m] row length (128 + 8 pad); 272B rows, gcd4 banks
#define B1STR  56    // B1 [n=96][k=48], 112B rows
#define B2STR 104    // B2 [n=48][k=96], 208B rows

__device__ float g_bufA[(size_t)NB_TOTAL * 64 * NC];
__device__ float g_bufB[(size_t)NB_TOTAL * 32 * NC];
__device__ __nv_bfloat16 g_B1h[96 * 48], g_B1l[96 * 48];
__device__ __nv_bfloat16 g_B2h[48 * 96], g_B2l[48 * 96];

// ---------------- smem layout (bytes) ---------------------------------------
#define OFF_B1H 0
#define OFF_B1L 10752
#define OFF_B2H 21504
#define OFF_B2L 31488
#define OFF_YH  41472          /* 48*136*2 = 13056 */
#define OFF_YL  54528
#define OFF_W   67584
#define DB1 10752
#define DB2  9984
#define DYL 13056

__host__ __device__ constexpr int smem_total_c(int CIN, int COUT, int MODE_IN) {
    return OFF_W + COUT * (CIN * 5 + 1) * 4 +
           (MODE_IN == 0 ? NC * ((MTILE / COUT) * CIN + 4) * 4 : 0);
}

// ---------------- PTX helpers ----------------------------------------------
__device__ __forceinline__ uint32_t smem_u32(const void* p) {
    uint32_t a;
    asm("{ .reg .u64 t; cvta.to.shared.u64 t, %1; cvt.u32.u64 %0, t; }"
        : "=r"(a) : "l"(p));
    return a;
}
__device__ __forceinline__ void ldsm_x4(uint32_t* r, uint32_t addr) {
    asm volatile("ldmatrix.sync.aligned.m8n8.x4.shared.b16 {%0,%1,%2,%3}, [%4];"
                 : "=r"(r[0]), "=r"(r[1]), "=r"(r[2]), "=r"(r[3]) : "r"(addr));
}
__device__ __forceinline__ void ldsm_x4t(uint32_t* r, uint32_t addr) {
    asm volatile("ldmatrix.sync.aligned.m8n8.x4.trans.shared.b16 {%0,%1,%2,%3}, [%4];"
                 : "=r"(r[0]), "=r"(r[1]), "=r"(r[2]), "=r"(r[3]) : "r"(addr));
}
__device__ __forceinline__ void mma_bf16(float* c, const uint32_t* a,
                                         uint32_t b0, uint32_t b1) {
    asm volatile(
        "mma.sync.aligned.m16n8k16.row.col.f32.bf16.bf16.f32 "
        "{%0,%1,%2,%3}, {%4,%5,%6,%7}, {%8,%9}, {%0,%1,%2,%3};"
        : "+f"(c[0]), "+f"(c[1]), "+f"(c[2]), "+f"(c[3])
        : "r"(a[0]), "r"(a[1]), "r"(a[2]), "r"(a[3]), "r"(b0), "r"(b1));
}
__device__ __forceinline__ uint32_t pack2bf(__nv_bfloat16 a, __nv_bfloat16 b) {
    return (uint32_t)__bfloat16_as_ushort(a) |
           ((uint32_t)__bfloat16_as_ushort(b) << 16);
}

// ---------------- problem constants -----------------------------------------
__host__ __device__ __forceinline__ constexpr int ggrp(int k) {
    return (k < 1) ? 0 : (k < 6) ? 1 : (k < 15) ? 2 : (k < 28) ? 3 : 4;
}
__device__ __forceinline__ float scl_of(int k) {
    const int g = ggrp(k);
    return g == 0 ? 1.77245385090552f
         : g == 1 ? 0.79266545952121f
         : g == 2 ? 0.59081795030184f
         : g == 3 ? 0.49159027f
         :          0.42988321f;
}

// ---------------- setup: pre-split B matrices to bf16 hi/lo -----------------
__global__ void build_B(const float* __restrict__ sft,
                        const float* __restrict__ isft) {
    const int tid = threadIdx.x;
    for (int i = tid; i < 96 * 48; i += 256) {     // B1[n=p(96)][k(48)]
        int n = i / 48, k = i - n * 48;
        float v = (n < ND && k < NC) ? isft[n * NC + k] : 0.f;
        __nv_bfloat16 hi = __float2bfloat16(v);
        g_B1h[i] = hi;
        g_B1l[i] = __float2bfloat16(v - __bfloat162float(hi));
    }
    for (int i = tid; i < 48 * 96; i += 256) {     // B2[n=k(48)][k=p(96)]
        int n = i / 96, p = i - n * 96;
        float v = (n < NC && p < ND) ? sft[n * ND + p] : 0.f;
        __nv_bfloat16 hi = __float2bfloat16(v);
        g_B2h[i] = hi;
        g_B2l[i] = __float2bfloat16(v - __bfloat162float(hi));
    }
}

// sconv over k in [K0,K0+KN): one thread, one row m; Y stored [k][m] coalesced
template <int K0, int KN, int CIN, int XSTR, int MODE_IN>
__device__ __forceinline__ void sconv_seg(const float* __restrict__ xb,
                                          const float* __restrict__ wb,
                                          __nv_bfloat16* __restrict__ yh,
                                          __nv_bfloat16* __restrict__ yl,
                                          int m) {
    constexpr size_t KS = (size_t)NB_TOTAL * CIN;
    float acc[KN];
#pragma unroll
    for (int kk = 0; kk < KN; kk++) acc[kk] = 0.f;
#pragma unroll 1
    for (int cb = 0; cb < CIN; cb += 4) {
        float wv[4][5];
#pragma unroll
        for (int cc = 0; cc < 4; cc++)
#pragma unroll
            for (int g = 0; g < 5; g++) wv[cc][g] = wb[(cb + cc) * 5 + g];
#pragma unroll
        for (int kk = 0; kk < KN; kk++) {
            float4 xv;
            if constexpr (MODE_IN == 0)
                xv = *reinterpret_cast<const float4*>(xb + (K0 + kk) * XSTR + cb);
            else
                xv = __ldg(reinterpret_cast<const float4*>(
                        xb + (size_t)(K0 + kk) * KS + cb));
            const int g = ggrp(K0 + kk);
            acc[kk] = fmaf(xv.x, wv[0][g], acc[kk]);
            acc[kk] = fmaf(xv.y, wv[1][g], acc[kk]);
            acc[kk] = fmaf(xv.z, wv[2][g], acc[kk]);
            acc[kk] = fmaf(xv.w, wv[3][g], acc[kk]);
        }
    }
#pragma unroll
    for (int kk = 0; kk < KN; kk++) {
        const float v = acc[kk] * scl_of(K0 + kk);
        const __nv_bfloat16 h = __float2bfloat16(v);
        yh[(K0 + kk) * MSTR + m] = h;
        yl[(K0 + kk) * MSTR + m] = __float2bfloat16(v - __bfloat162float(h));
    }
}

// ---------------- per-layer persistent kernel -------------------------------
template <int CIN, int COUT, int MODE_IN, int MODE_OUT>
__global__ void __launch_bounds__(NTT, 2)
scnn_layer(const float* __restrict__ in, const float* __restrict__ w,
           float* __restrict__ out, int ntiles) {
    constexpr int TB   = MTILE / COUT;
    constexpr int MIN_ = TB * CIN;
    constexpr int XSTR = MIN_ + 4;
    constexpr int WSTR = CIN * 5 + 1;
    constexpr int OFF_X_ = OFF_W + COUT * WSTR * 4;
    static_assert(MTILE % COUT == 0 && CIN % 4 == 0, "cfg");

    extern __shared__ char smc[];
    const uint32_t sb = smem_u32(smc);
    const int tid = threadIdx.x, wid = tid >> 5, lane = tid & 31;

    __nv_bfloat16* Yh = (__nv_bfloat16*)(smc + OFF_YH);
    __nv_bfloat16* Yl = (__nv_bfloat16*)(smc + OFF_YL);
    float* s_w = (float*)(smc + OFF_W);
    float* s_x = (float*)(smc + OFF_X_);

    // ---- one-time setup: zero Y (covers k-pads 45..47), copy B, load W -----
    for (int i = tid; i < (OFF_W - OFF_YH) / 4; i += NTT)
        ((uint32_t*)(smc + OFF_YH))[i] = 0;
    {
        const uint32_t* s1h = (const uint32_t*)g_B1h;
        const uint32_t* s1l = (const uint32_t*)g_B1l;
        uint32_t* d1h = (uint32_t*)(smc + OFF_B1H);
        uint32_t* d1l = (uint32_t*)(smc + OFF_B1L);
        for (int i = tid; i < 96 * 24; i += NTT) {
            int n = i / 24, kk = i - n * 24;
            d1h[(n * B1STR) / 2 + kk] = s1h[i];
            d1l[(n * B1STR) / 2 + kk] = s1l[i];
        }
        const uint32_t* s2h = (const uint32_t*)g_B2h;
        const uint32_t* s2l = (const uint32_t*)g_B2l;
        uint32_t* d2h = (uint32_t*)(smc + OFF_B2H);
        uint32_t* d2l = (uint32_t*)(smc + OFF_B2L);
        for (int i = tid; i < 48 * 48; i += NTT) {
            int n = i / 48, kk = i - n * 48;
            d2h[(n * B2STR) / 2 + kk] = s2h[i];
            d2l[(n * B2STR) / 2 + kk] = s2l[i];
        }
    }
    for (int i = tid; i < COUT * CIN * 5; i += NTT) {
        int o = i / (CIN * 5);
        s_w[o * WSTR + (i - o * (CIN * 5))] = w[i];
    }

    // ---- loop-invariant addressing (8 warps, m16 each) ---------------------
    const int mb = wid * 16;
    const int g = lane >> 3, rr = lane & 7;
    const int qr = lane >> 2, qc = lane & 3;

    // A (Y) trans load: Y is [k][m]; 8-lane groups pick (k-half, m-half)
    const uint32_t aYt = sb + OFF_YH +
        (((g >> 1) * 8 + rr) * MSTR + mb + (g & 1) * 8) * 2;
    const uint32_t bB1 = sb + OFF_B1H +
        (((g >> 1) * 8 + rr) * B1STR + (g & 1) * 8) * 2;
    const uint32_t bB2 = sb + OFF_B2H +
        (((g >> 1) * 8 + rr) * B2STR + (g & 1) * 8) * 2;

    // sconv mapping: 256 threads over 128 rows x 2 k-segments
    const int rS = tid & (MTILE - 1);
    const int segS = tid >> 7;                 // warp-uniform
    const int tS = rS / COUT, oS = rS % COUT;
    const float* wbS = s_w + oS * WSTR;

    // ---- L1 only: stage first tile's x (guarded) ---------------------------
    int t = blockIdx.x;
    if constexpr (MODE_IN == 0) {
        if (t < ntiles) {
            const size_t bi = (size_t)t * (MIN_ * NC);
            for (int i = tid; i < MIN_ * NC; i += NTT) {
                int m = i / NC, k = i - m * NC;
                int b = t * TB + m / CIN;
                s_x[k * XSTR + m] = (b < NB_TOTAL) ? in[bi + i] : 0.f;
            }
        }
    }
    __syncthreads();

    // ---- persistent tile loop ----------------------------------------------
    for (; t < ntiles; t += gridDim.x) {
        // phase A: sconv -> Y[k][m]
        {
            const float* xb;
            if constexpr (MODE_IN == 0) {
                xb = s_x + tS * CIN;
            } else {
                int b = t * TB + tS;
                if (b >= NB_TOTAL) b = NB_TOTAL - 1;   // clamp; store guarded
                xb = in + (size_t)b * CIN;
            }
            if (segS == 0)
                sconv_seg< 0, 22, CIN, XSTR, MODE_IN>(xb, wbS, Yh, Yl, rS);
            else
                sconv_seg<22, 23, CIN, XSTR, MODE_IN>(xb, wbS, Yh, Yl, rS);
        }
        __syncthreads();

        // phase B: GEMM1 (m16 x full N=96), c1 in registers
        float c1[12][4];
#pragma unroll
        for (int i = 0; i < 12; i++)
#pragma unroll
            for (int j = 0; j < 4; j++) c1[i][j] = 0.f;

#pragma unroll
        for (int ks = 0; ks < 3; ks++) {
            uint32_t ah[4], al[4];
            ldsm_x4t(ah, aYt + ks * (16 * MSTR * 2));
            ldsm_x4t(al, aYt + ks * (16 * MSTR * 2) + DYL);
#pragma unroll
            for (int np = 0; np < 6; np++) {
                const uint32_t bo = bB1 + ks * 32 + np * (16 * B1STR * 2);
                uint32_t bh[4], bl[4];
                ldsm_x4(bh, bo);
                ldsm_x4(bl, bo + DB1);
                mma_bf16(c1[2 * np], ah, bh[0], bh[1]);
                mma_bf16(c1[2 * np], ah, bl[0], bl[1]);
                mma_bf16(c1[2 * np], al, bh[0], bh[1]);
                mma_bf16(c1[2 * np + 1], ah, bh[2], bh[3]);
                mma_bf16(c1[2 * np + 1], ah, bl[2], bl[3]);
                mma_bf16(c1[2 * np + 1], al, bh[2], bh[3]);
            }
        }

        // L1 only: prefetch next tile's x (x dead after sconv)
        if constexpr (MODE_IN == 0) {
            const int tn = t + gridDim.x;
            if (tn < ntiles) {
                const size_t bi = (size_t)tn * (MIN_ * NC);
                for (int i = tid; i < MIN_ * NC; i += NTT) {
                    int m = i / NC, k = i - m * NC;
                    int b = tn * TB + m / CIN;
                    s_x[k * XSTR + m] = (b < NB_TOTAL) ? in[bi + i] : 0.f;
                }
            }
        }

        // phase C: GEMM2 (m16 x full N=48), register repack from c1
        float c2[6][4];
#pragma unroll
        for (int i = 0; i < 6; i++)
#pragma unroll
            for (int j = 0; j < 4; j++) c2[i][j] = 0.f;

#pragma unroll
        for (int kc = 0; kc < 6; kc++) {
            uint32_t a2h[4], a2l[4];
#pragma unroll
            for (int u = 0; u < 2; u++)
#pragma unroll
                for (int v = 0; v < 2; v++) {
                    const float p0 = fmaxf(c1[2 * kc + u][2 * v], 0.f);
                    const float p1 = fmaxf(c1[2 * kc + u][2 * v + 1], 0.f);
                    const __nv_bfloat16 h0 = __float2bfloat16(p0);
                    const __nv_bfloat16 h1 = __float2bfloat16(p1);
                    a2h[2 * u + v] = pack2bf(h0, h1);
                    a2l[2 * u + v] =
                        pack2bf(__float2bfloat16(p0 - __bfloat162float(h0)),
                                __float2bfloat16(p1 - __bfloat162float(h1)));
                }
#pragma unroll
            for (int np = 0; np < 3; np++) {
                const uint32_t bo = bB2 + kc * 32 + np * (16 * B2STR * 2);
                uint32_t bh[4], bl[4];
                ldsm_x4(bh, bo);
                ldsm_x4(bl, bo + DB2);
                mma_bf16(c2[2 * np], a2h, bh[0], bh[1]);
                mma_bf16(c2[2 * np], a2h, bl[0], bl[1]);
                mma_bf16(c2[2 * np], a2l, bh[0], bh[1]);
                mma_bf16(c2[2 * np + 1], a2h, bh[2], bh[3]);
                mma_bf16(c2[2 * np + 1], a2h, bl[2], bl[3]);
                mma_bf16(c2[2 * np + 1], a2l, bh[2], bh[3]);
            }
        }

        // phase D: store c2 straight to gmem (guarded)
#pragma unroll
        for (int j = 0; j < 6; j++) {
            const int col = 8 * j + 2 * qc;
#pragma unroll
            for (int h = 0; h < 2; h++) {
                const int row = mb + qr + 8 * h;
                const float v0 = c2[j][2 * h];
                const float v1 = c2[j][2 * h + 1];
                if constexpr (MODE_OUT == 1) {       // [k][b][ch]
                    const int b = t * TB + row / COUT;
                    const int ch = row % COUT;
                    if (b < NB_TOTAL) {
                        if (col < NC)
                            out[((size_t)col * NB_TOTAL + b) * COUT + ch] = v0;
                        if (col + 1 < NC)
                            out[((size_t)(col + 1) * NB_TOTAL + b) * COUT + ch] = v1;
                    }
                } else {                             // [b][ch][k] (L6)
                    if (t * TB + row / COUT < NB_TOTAL) {
                        const size_t ro = ((size_t)t * MTILE + row) * NC;
                        if (col < NC)     out[ro + col]     = v0;
                        if (col + 1 < NC) out[ro + col + 1] = v1;
                    }
                }
            }
        }
        __syncthreads();   // protect Y before next tile's sconv
    }
}

// ---------------- host ------------------------------------------------------
extern "C" void kernel_launch(void* const* d_in, const int* in_sizes, int n_in,
                              void* d_out, int out_size) {
    (void)in_sizes; (void)n_in; (void)out_size;

    const float* x    = (const float*)d_in[0];
    const float* sft  = (const float*)d_in[1];
    const float* isft = (const float*)d_in[2];
    const float* w1   = (const float*)d_in[3];
    const float* w2   = (const float*)d_in[4];
    const float* w3   = (const float*)d_in[5];
    const float* w4   = (const float*)d_in[6];
    const float* w5   = (const float*)d_in[7];
    const float* w6   = (const float*)d_in[8];
    float* out = (float*)d_out;

    float *bufA = nullptr, *bufB = nullptr;
    cudaGetSymbolAddress((void**)&bufA, g_bufA);
    cudaGetSymbolAddress((void**)&bufB, g_bufB);

    cudaFuncSetAttribute((const void*)scnn_layer<4, 16, 0, 1>,
        cudaFuncAttributeMaxDynamicSharedMemorySize, smem_total_c(4, 16, 0));
    cudaFuncSetAttribute((const void*)scnn_layer<16, 32, 1, 1>,
        cudaFuncAttributeMaxDynamicSharedMemorySize, smem_total_c(16, 32, 1));
    cudaFuncSetAttribute((const void*)scnn_layer<32, 64, 1, 1>,
        cudaFuncAttributeMaxDynamicSharedMemorySize, smem_total_c(32, 64, 1));
    cudaFuncSetAttribute((const void*)scnn_layer<64, 32, 1, 1>,
        cudaFuncAttributeMaxDynamicSharedMemorySize, smem_total_c(64, 32, 1));
    cudaFuncSetAttribute((const void*)scnn_layer<32, 16, 1, 1>,
        cudaFuncAttributeMaxDynamicSharedMemorySize, smem_total_c(32, 16, 1));
    cudaFuncSetAttribute((const void*)scnn_layer<16, 4, 1, 0>,
        cudaFuncAttributeMaxDynamicSharedMemorySize, smem_total_c(16, 4, 1));

    build_B<<<1, 256>>>(sft, isft);

    const int GRID2 = 296;   // 2 CTAs/SM
    // TB = 128/COUT -> tiles: L1 6250, L2 12500, L3 25000, L4 12500, L5 6250,
    // L6 ceil(50000/32)=1563 (guarded tail)
    scnn_layer<4, 16, 0, 1><<<GRID2, NTT, smem_total_c(4, 16, 0)>>>(
        x, w1, bufA, NB_TOTAL / 8);
    scnn_layer<16, 32, 1, 1><<<GRID2, NTT, smem_total_c(16, 32, 1)>>>(
        bufA, w2, bufB, NB_TOTAL / 4);
    scnn_layer<32, 64, 1, 1><<<GRID2, NTT, smem_total_c(32, 64, 1)>>>(
        bufB, w3, bufA, NB_TOTAL / 2);
    scnn_layer<64, 32, 1, 1><<<GRID2, NTT, smem_total_c(64, 32, 1)>>>(
        bufA, w4, bufB, NB_TOTAL / 4);
    scnn_layer<32, 16, 1, 1><<<GRID2, NTT, smem_total_c(32, 16, 1)>>>(
        bufB, w5, bufA, NB_TOTAL / 8);
    scnn_layer<16, 4, 1, 0><<<GRID2, NTT, smem_total_c(16, 4, 1)>>>(
        bufA, w6, out, (NB_TOTAL + 31) / 32);
}

// round 14
// speedup vs baseline: 1.4555x; 1.2340x over previous
#include <cuda_runtime.h>
#include <cuda_bf16.h>
#include <cstdint>
#include <cstddef>

// ----------------------------------------------------------------------------
// SCNN via warp-level HMMA (mma.sync bf16, fp32 accum), persistent CTAs.
// R13 = R12 (m16 x full-N register-fused, 2 CTAs/SM, transposed Y) +
// sconv operand-traffic cuts: 2 rows/thread (x float4 shared across rows,
// halves x broadcast-LDG wavefronts) and 4-way k-split with g-selective
// weight loads (skips unused degree groups per segment).
// ----------------------------------------------------------------------------

#define NB_TOTAL 50000
#define NC 45
#define ND 90
#define NTT 256
#define MTILE 128
#define MSTR 136     // Y [k][m] row length (128 + 8 pad); 272B rows
#define B1STR  56    // B1 [n=96][k=48], 112B rows
#define B2STR 104    // B2 [n=48][k=96], 208B rows

__device__ float g_bufA[(size_t)NB_TOTAL * 64 * NC];
__device__ float g_bufB[(size_t)NB_TOTAL * 32 * NC];
__device__ __nv_bfloat16 g_B1h[96 * 48], g_B1l[96 * 48];
__device__ __nv_bfloat16 g_B2h[48 * 96], g_B2l[48 * 96];

// ---------------- smem layout (bytes) ---------------------------------------
#define OFF_B1H 0
#define OFF_B1L 10752
#define OFF_B2H 21504
#define OFF_B2L 31488
#define OFF_YH  41472          /* 48*136*2 = 13056 */
#define OFF_YL  54528
#define OFF_W   67584
#define DB1 10752
#define DB2  9984
#define DYL 13056

__host__ __device__ constexpr int smem_total_c(int CIN, int COUT, int MODE_IN) {
    return OFF_W + COUT * (CIN * 5 + 1) * 4 +
           (MODE_IN == 0 ? NC * ((MTILE / COUT) * CIN + 4) * 4 : 0);
}

// ---------------- PTX helpers ----------------------------------------------
__device__ __forceinline__ uint32_t smem_u32(const void* p) {
    uint32_t a;
    asm("{ .reg .u64 t; cvta.to.shared.u64 t, %1; cvt.u32.u64 %0, t; }"
        : "=r"(a) : "l"(p));
    return a;
}
__device__ __forceinline__ void ldsm_x4(uint32_t* r, uint32_t addr) {
    asm volatile("ldmatrix.sync.aligned.m8n8.x4.shared.b16 {%0,%1,%2,%3}, [%4];"
                 : "=r"(r[0]), "=r"(r[1]), "=r"(r[2]), "=r"(r[3]) : "r"(addr));
}
__device__ __forceinline__ void ldsm_x4t(uint32_t* r, uint32_t addr) {
    asm volatile("ldmatrix.sync.aligned.m8n8.x4.trans.shared.b16 {%0,%1,%2,%3}, [%4];"
                 : "=r"(r[0]), "=r"(r[1]), "=r"(r[2]), "=r"(r[3]) : "r"(addr));
}
__device__ __forceinline__ void mma_bf16(float* c, const uint32_t* a,
                                         uint32_t b0, uint32_t b1) {
    asm volatile(
        "mma.sync.aligned.m16n8k16.row.col.f32.bf16.bf16.f32 "
        "{%0,%1,%2,%3}, {%4,%5,%6,%7}, {%8,%9}, {%0,%1,%2,%3};"
        : "+f"(c[0]), "+f"(c[1]), "+f"(c[2]), "+f"(c[3])
        : "r"(a[0]), "r"(a[1]), "r"(a[2]), "r"(a[3]), "r"(b0), "r"(b1));
}
__device__ __forceinline__ uint32_t pack2bf(__nv_bfloat16 a, __nv_bfloat16 b) {
    return (uint32_t)__bfloat16_as_ushort(a) |
           ((uint32_t)__bfloat16_as_ushort(b) << 16);
}

// ---------------- problem constants -----------------------------------------
__host__ __device__ __forceinline__ constexpr int ggrp(int k) {
    return (k < 1) ? 0 : (k < 6) ? 1 : (k < 15) ? 2 : (k < 28) ? 3 : 4;
}
__device__ __forceinline__ float scl_of(int k) {
    const int g = ggrp(k);
    return g == 0 ? 1.77245385090552f
         : g == 1 ? 0.79266545952121f
         : g == 2 ? 0.59081795030184f
         : g == 3 ? 0.49159027f
         :          0.42988321f;
}

// ---------------- setup: pre-split B matrices to bf16 hi/lo -----------------
__global__ void build_B(const float* __restrict__ sft,
                        const float* __restrict__ isft) {
    const int tid = threadIdx.x;
    for (int i = tid; i < 96 * 48; i += 256) {     // B1[n=p(96)][k(48)]
        int n = i / 48, k = i - n * 48;
        float v = (n < ND && k < NC) ? isft[n * NC + k] : 0.f;
        __nv_bfloat16 hi = __float2bfloat16(v);
        g_B1h[i] = hi;
        g_B1l[i] = __float2bfloat16(v - __bfloat162float(hi));
    }
    for (int i = tid; i < 48 * 96; i += 256) {     // B2[n=k(48)][k=p(96)]
        int n = i / 96, p = i - n * 96;
        float v = (n < NC && p < ND) ? sft[n * ND + p] : 0.f;
        __nv_bfloat16 hi = __float2bfloat16(v);
        g_B2h[i] = hi;
        g_B2l[i] = __float2bfloat16(v - __bfloat162float(hi));
    }
}

// sconv over k in [K0,K0+KN), groups [G0,G0+GN): one thread, TWO rows r0,r1
// sharing the same x (same batch element). Y stored [k][m] (coalesced).
template <int K0, int KN, int G0, int GN, int CIN, int XSTR, int MODE_IN>
__device__ __forceinline__ void sconv_seg2(const float* __restrict__ xb,
                                           const float* __restrict__ wb0,
                                           const float* __restrict__ wb1,
                                           __nv_bfloat16* __restrict__ yh,
                                           __nv_bfloat16* __restrict__ yl,
                                           int r0, int r1) {
    constexpr size_t KS = (size_t)NB_TOTAL * CIN;
    float acc[2][KN];
#pragma unroll
    for (int kk = 0; kk < KN; kk++) { acc[0][kk] = 0.f; acc[1][kk] = 0.f; }
#pragma unroll 1
    for (int cb = 0; cb < CIN; cb += 4) {
        float wv[2][4][GN];
#pragma unroll
        for (int cc = 0; cc < 4; cc++)
#pragma unroll
            for (int gi = 0; gi < GN; gi++) {
                wv[0][cc][gi] = wb0[(cb + cc) * 5 + G0 + gi];
                wv[1][cc][gi] = wb1[(cb + cc) * 5 + G0 + gi];
            }
#pragma unroll
        for (int kk = 0; kk < KN; kk++) {
            float4 xv;
            if constexpr (MODE_IN == 0)
                xv = *reinterpret_cast<const float4*>(xb + (K0 + kk) * XSTR + cb);
            else
                xv = __ldg(reinterpret_cast<const float4*>(
                        xb + (size_t)(K0 + kk) * KS + cb));
            const int gi = ggrp(K0 + kk) - G0;   // constexpr after unroll
#pragma unroll
            for (int rr2 = 0; rr2 < 2; rr2++) {
                acc[rr2][kk] = fmaf(xv.x, wv[rr2][0][gi], acc[rr2][kk]);
                acc[rr2][kk] = fmaf(xv.y, wv[rr2][1][gi], acc[rr2][kk]);
                acc[rr2][kk] = fmaf(xv.z, wv[rr2][2][gi], acc[rr2][kk]);
                acc[rr2][kk] = fmaf(xv.w, wv[rr2][3][gi], acc[rr2][kk]);
            }
        }
    }
#pragma unroll
    for (int kk = 0; kk < KN; kk++) {
        const float s = scl_of(K0 + kk);
        const float v0 = acc[0][kk] * s;
        const float v1 = acc[1][kk] * s;
        const __nv_bfloat16 h0 = __float2bfloat16(v0);
        const __nv_bfloat16 h1 = __float2bfloat16(v1);
        yh[(K0 + kk) * MSTR + r0] = h0;
        yh[(K0 + kk) * MSTR + r1] = h1;
        yl[(K0 + kk) * MSTR + r0] = __float2bfloat16(v0 - __bfloat162float(h0));
        yl[(K0 + kk) * MSTR + r1] = __float2bfloat16(v1 - __bfloat162float(h1));
    }
}

// ---------------- per-layer persistent kernel -------------------------------
template <int CIN, int COUT, int MODE_IN, int MODE_OUT>
__global__ void __launch_bounds__(NTT, 2)
scnn_layer(const float* __restrict__ in, const float* __restrict__ w,
           float* __restrict__ out, int ntiles) {
    constexpr int TB   = MTILE / COUT;
    constexpr int MIN_ = TB * CIN;
    constexpr int XSTR = MIN_ + 4;
    constexpr int WSTR = CIN * 5 + 1;
    constexpr int HALF = COUT / 2;
    constexpr int OFF_X_ = OFF_W + COUT * WSTR * 4;
    static_assert(MTILE % COUT == 0 && CIN % 4 == 0 && COUT % 2 == 0, "cfg");

    extern __shared__ char smc[];
    const uint32_t sb = smem_u32(smc);
    const int tid = threadIdx.x, wid = tid >> 5, lane = tid & 31;

    __nv_bfloat16* Yh = (__nv_bfloat16*)(smc + OFF_YH);
    __nv_bfloat16* Yl = (__nv_bfloat16*)(smc + OFF_YL);
    float* s_w = (float*)(smc + OFF_W);
    float* s_x = (float*)(smc + OFF_X_);

    // ---- one-time setup: zero Y (covers k-pads 45..47), copy B, load W -----
    for (int i = tid; i < (OFF_W - OFF_YH) / 4; i += NTT)
        ((uint32_t*)(smc + OFF_YH))[i] = 0;
    {
        const uint32_t* s1h = (const uint32_t*)g_B1h;
        const uint32_t* s1l = (const uint32_t*)g_B1l;
        uint32_t* d1h = (uint32_t*)(smc + OFF_B1H);
        uint32_t* d1l = (uint32_t*)(smc + OFF_B1L);
        for (int i = tid; i < 96 * 24; i += NTT) {
            int n = i / 24, kk = i - n * 24;
            d1h[(n * B1STR) / 2 + kk] = s1h[i];
            d1l[(n * B1STR) / 2 + kk] = s1l[i];
        }
        const uint32_t* s2h = (const uint32_t*)g_B2h;
        const uint32_t* s2l = (const uint32_t*)g_B2l;
        uint32_t* d2h = (uint32_t*)(smc + OFF_B2H);
        uint32_t* d2l = (uint32_t*)(smc + OFF_B2L);
        for (int i = tid; i < 48 * 48; i += NTT) {
            int n = i / 48, kk = i - n * 48;
            d2h[(n * B2STR) / 2 + kk] = s2h[i];
            d2l[(n * B2STR) / 2 + kk] = s2l[i];
        }
    }
    for (int i = tid; i < COUT * CIN * 5; i += NTT) {
        int o = i / (CIN * 5);
        s_w[o * WSTR + (i - o * (CIN * 5))] = w[i];
    }

    // ---- loop-invariant addressing (8 warps, m16 each for GEMMs) -----------
    const int mb = wid * 16;
    const int g = lane >> 3, rr = lane & 7;
    const int qr = lane >> 2, qc = lane & 3;

    const uint32_t aYt = sb + OFF_YH +
        (((g >> 1) * 8 + rr) * MSTR + mb + (g & 1) * 8) * 2;
    const uint32_t bB1 = sb + OFF_B1H +
        (((g >> 1) * 8 + rr) * B1STR + (g & 1) * 8) * 2;
    const uint32_t bB2 = sb + OFF_B2H +
        (((g >> 1) * 8 + rr) * B2STR + (g & 1) * 8) * 2;

    // sconv mapping: 256 threads = 64 row-pairs x 4 k-segments
    const int q   = tid >> 6;              // k-segment, warp-uniform
    const int idx = tid & 63;
    const int tS  = idx / HALF;            // batch element within tile
    const int oS  = idx % HALF;
    const int r0  = tS * COUT + oS;
    const int r1  = r0 + HALF;
    const float* wb0 = s_w + oS * WSTR;
    const float* wb1 = s_w + (oS + HALF) * WSTR;

    // ---- L1 only: stage first tile's x (guarded) ---------------------------
    int t = blockIdx.x;
    if constexpr (MODE_IN == 0) {
        if (t < ntiles) {
            const size_t bi = (size_t)t * (MIN_ * NC);
            for (int i = tid; i < MIN_ * NC; i += NTT) {
                int m = i / NC, k = i - m * NC;
                int b = t * TB + m / CIN;
                s_x[k * XSTR + m] = (b < NB_TOTAL) ? in[bi + i] : 0.f;
            }
        }
    }
    __syncthreads();

    // ---- persistent tile loop ----------------------------------------------
    for (; t < ntiles; t += gridDim.x) {
        // phase A: sconv -> Y[k][m], 2 rows per thread, g-selective weights
        {
            const float* xb;
            if constexpr (MODE_IN == 0) {
                xb = s_x + tS * CIN;
            } else {
                int b = t * TB + tS;
                if (b >= NB_TOTAL) b = NB_TOTAL - 1;   // clamp; store guarded
                xb = in + (size_t)b * CIN;
            }
            if      (q == 0) sconv_seg2< 0, 12, 0, 3, CIN, XSTR, MODE_IN>(
                                 xb, wb0, wb1, Yh, Yl, r0, r1);
            else if (q == 1) sconv_seg2<12, 11, 2, 2, CIN, XSTR, MODE_IN>(
                                 xb, wb0, wb1, Yh, Yl, r0, r1);
            else if (q == 2) sconv_seg2<23, 11, 3, 2, CIN, XSTR, MODE_IN>(
                                 xb, wb0, wb1, Yh, Yl, r0, r1);
            else             sconv_seg2<34, 11, 4, 1, CIN, XSTR, MODE_IN>(
                                 xb, wb0, wb1, Yh, Yl, r0, r1);
        }
        __syncthreads();

        // phase B: GEMM1 (m16 x full N=96), c1 in registers
        float c1[12][4];
#pragma unroll
        for (int i = 0; i < 12; i++)
#pragma unroll
            for (int j = 0; j < 4; j++) c1[i][j] = 0.f;

#pragma unroll
        for (int ks = 0; ks < 3; ks++) {
            uint32_t ah[4], al[4];
            ldsm_x4t(ah, aYt + ks * (16 * MSTR * 2));
            ldsm_x4t(al, aYt + ks * (16 * MSTR * 2) + DYL);
#pragma unroll
            for (int np = 0; np < 6; np++) {
                const uint32_t bo = bB1 + ks * 32 + np * (16 * B1STR * 2);
                uint32_t bh[4], bl[4];
                ldsm_x4(bh, bo);
                ldsm_x4(bl, bo + DB1);
                mma_bf16(c1[2 * np], ah, bh[0], bh[1]);
                mma_bf16(c1[2 * np], ah, bl[0], bl[1]);
                mma_bf16(c1[2 * np], al, bh[0], bh[1]);
                mma_bf16(c1[2 * np + 1], ah, bh[2], bh[3]);
                mma_bf16(c1[2 * np + 1], ah, bl[2], bl[3]);
                mma_bf16(c1[2 * np + 1], al, bh[2], bh[3]);
            }
        }

        // L1 only: prefetch next tile's x (x dead after sconv)
        if constexpr (MODE_IN == 0) {
            const int tn = t + gridDim.x;
            if (tn < ntiles) {
                const size_t bi = (size_t)tn * (MIN_ * NC);
                for (int i = tid; i < MIN_ * NC; i += NTT) {
                    int m = i / NC, k = i - m * NC;
                    int b = tn * TB + m / CIN;
                    s_x[k * XSTR + m] = (b < NB_TOTAL) ? in[bi + i] : 0.f;
                }
            }
        }

        // phase C: GEMM2 (m16 x full N=48), register repack from c1
        float c2[6][4];
#pragma unroll
        for (int i = 0; i < 6; i++)
#pragma unroll
            for (int j = 0; j < 4; j++) c2[i][j] = 0.f;

#pragma unroll
        for (int kc = 0; kc < 6; kc++) {
            uint32_t a2h[4], a2l[4];
#pragma unroll
            for (int u = 0; u < 2; u++)
#pragma unroll
                for (int v = 0; v < 2; v++) {
                    const float p0 = fmaxf(c1[2 * kc + u][2 * v], 0.f);
                    const float p1 = fmaxf(c1[2 * kc + u][2 * v + 1], 0.f);
                    const __nv_bfloat16 h0 = __float2bfloat16(p0);
                    const __nv_bfloat16 h1 = __float2bfloat16(p1);
                    a2h[2 * u + v] = pack2bf(h0, h1);
                    a2l[2 * u + v] =
                        pack2bf(__float2bfloat16(p0 - __bfloat162float(h0)),
                                __float2bfloat16(p1 - __bfloat162float(h1)));
                }
#pragma unroll
            for (int np = 0; np < 3; np++) {
                const uint32_t bo = bB2 + kc * 32 + np * (16 * B2STR * 2);
                uint32_t bh[4], bl[4];
                ldsm_x4(bh, bo);
                ldsm_x4(bl, bo + DB2);
                mma_bf16(c2[2 * np], a2h, bh[0], bh[1]);
                mma_bf16(c2[2 * np], a2h, bl[0], bl[1]);
                mma_bf16(c2[2 * np], a2l, bh[0], bh[1]);
                mma_bf16(c2[2 * np + 1], a2h, bh[2], bh[3]);
                mma_bf16(c2[2 * np + 1], a2h, bl[2], bl[3]);
                mma_bf16(c2[2 * np + 1], a2l, bh[2], bh[3]);
            }
        }

        // phase D: store c2 straight to gmem (guarded)
#pragma unroll
        for (int j = 0; j < 6; j++) {
            const int col = 8 * j + 2 * qc;
#pragma unroll
            for (int h = 0; h < 2; h++) {
                const int row = mb + qr + 8 * h;
                const float v0 = c2[j][2 * h];
                const float v1 = c2[j][2 * h + 1];
                if constexpr (MODE_OUT == 1) {       // [k][b][ch]
                    const int b = t * TB + row / COUT;
                    const int ch = row % COUT;
                    if (b < NB_TOTAL) {
                        if (col < NC)
                            out[((size_t)col * NB_TOTAL + b) * COUT + ch] = v0;
                        if (col + 1 < NC)
                            out[((size_t)(col + 1) * NB_TOTAL + b) * COUT + ch] = v1;
                    }
                } else {                             // [b][ch][k] (L6)
                    if (t * TB + row / COUT < NB_TOTAL) {
                        const size_t ro = ((size_t)t * MTILE + row) * NC;
                        if (col < NC)     out[ro + col]     = v0;
                        if (col + 1 < NC) out[ro + col + 1] = v1;
                    }
                }
            }
        }
        __syncthreads();   // protect Y before next tile's sconv
    }
}

// ---------------- host ------------------------------------------------------
extern "C" void kernel_launch(void* const* d_in, const int* in_sizes, int n_in,
                              void* d_out, int out_size) {
    (void)in_sizes; (void)n_in; (void)out_size;

    const float* x    = (const float*)d_in[0];
    const float* sft  = (const float*)d_in[1];
    const float* isft = (const float*)d_in[2];
    const float* w1   = (const float*)d_in[3];
    const float* w2   = (const float*)d_in[4];
    const float* w3   = (const float*)d_in[5];
    const float* w4   = (const float*)d_in[6];
    const float* w5   = (const float*)d_in[7];
    const float* w6   = (const float*)d_in[8];
    float* out = (float*)d_out;

    float *bufA = nullptr, *bufB = nullptr;
    cudaGetSymbolAddress((void**)&bufA, g_bufA);
    cudaGetSymbolAddress((void**)&bufB, g_bufB);

    cudaFuncSetAttribute((const void*)scnn_layer<4, 16, 0, 1>,
        cudaFuncAttributeMaxDynamicSharedMemorySize, smem_total_c(4, 16, 0));
    cudaFuncSetAttribute((const void*)scnn_layer<16, 32, 1, 1>,
        cudaFuncAttributeMaxDynamicSharedMemorySize, smem_total_c(16, 32, 1));
    cudaFuncSetAttribute((const void*)scnn_layer<32, 64, 1, 1>,
        cudaFuncAttributeMaxDynamicSharedMemorySize, smem_total_c(32, 64, 1));
    cudaFuncSetAttribute((const void*)scnn_layer<64, 32, 1, 1>,
        cudaFuncAttributeMaxDynamicSharedMemorySize, smem_total_c(64, 32, 1));
    cudaFuncSetAttribute((const void*)scnn_layer<32, 16, 1, 1>,
        cudaFuncAttributeMaxDynamicSharedMemorySize, smem_total_c(32, 16, 1));
    cudaFuncSetAttribute((const void*)scnn_layer<16, 4, 1, 0>,
        cudaFuncAttributeMaxDynamicSharedMemorySize, smem_total_c(16, 4, 1));

    build_B<<<1, 256>>>(sft, isft);

    const int GRID2 = 296;   // 2 CTAs/SM
    scnn_layer<4, 16, 0, 1><<<GRID2, NTT, smem_total_c(4, 16, 0)>>>(
        x, w1, bufA, NB_TOTAL / 8);
    scnn_layer<16, 32, 1, 1><<<GRID2, NTT, smem_total_c(16, 32, 1)>>>(
        bufA, w2, bufB, NB_TOTAL / 4);
    scnn_layer<32, 64, 1, 1><<<GRID2, NTT, smem_total_c(32, 64, 1)>>>(
        bufB, w3, bufA, NB_TOTAL / 2);
    scnn_layer<64, 32, 1, 1><<<GRID2, NTT, smem_total_c(64, 32, 1)>>>(
        bufA, w4, bufB, NB_TOTAL / 4);
    scnn_layer<32, 16, 1, 1><<<GRID2, NTT, smem_total_c(32, 16, 1)>>>(
        bufB, w5, bufA, NB_TOTAL / 8);
    scnn_layer<16, 4, 1, 0><<<GRID2, NTT, smem_total_c(16, 4, 1)>>>(
        bufA, w6, out, (NB_TOTAL + 31) / 32);
}

// round 15
// speedup vs baseline: 1.5567x; 1.0695x over previous
#include <cuda_runtime.h>
#include <cuda_bf16.h>
#include <cstdint>
#include <cstddef>

// ----------------------------------------------------------------------------
// SCNN via warp-level HMMA (mma.sync bf16, fp32 accum), persistent CTAs.
// R14: M=256 tile, 8 warps x m32, pc-fused GEMM1->GEMM2 (c1 transient per p16
// chunk -> no full c1, no exchange), W evicted from smem to a gmem image
// Wexp[g][c][o] loaded as float4 (4 output rows per thread), 4-row sconv.
// 256 threads, 2 CTAs/SM. 2 barriers per 256-row tile.
// ----------------------------------------------------------------------------

#define NB_TOTAL 50000
#define NC 45
#define ND 90
#define NTT 256
#define MTILE 256
#define MSTR 264     // Y [k][m] row length (256 + 8 pad); 528B rows
#define B1STR  56    // B1 [n=96][k=48], 112B rows
#define B2STR 104    // B2 [n=48][k=96], 208B rows

__device__ float g_bufA[(size_t)NB_TOTAL * 64 * NC];
__device__ float g_bufB[(size_t)NB_TOTAL * 32 * NC];
__device__ __nv_bfloat16 g_B1h[96 * 48], g_B1l[96 * 48];
__device__ __nv_bfloat16 g_B2h[48 * 96], g_B2l[48 * 96];
// Expanded weights, layout [g][c][o] per layer (o contiguous)
__device__ float g_Wexp[26240];
// layer offsets: L1 0, L2 320, L3 2880, L4 13120, L5 23360, L6 25920

// ---------------- smem layout (bytes) ---------------------------------------
#define OFF_B1H 0
#define OFF_B1L 10752
#define OFF_B2H 21504
#define OFF_B2L 31488
#define OFF_YH  41472          /* 48*264*2 = 25344 */
#define OFF_YL  66816
#define OFF_X   92160          /* L1 only */
#define DB1 10752
#define DB2  9984
#define DYL 25344

__host__ __device__ constexpr int smem_total_c(int CIN, int COUT, int MODE_IN) {
    return OFF_X + (MODE_IN == 0 ? NC * ((MTILE / COUT) * CIN + 4) * 4 : 0);
}

// ---------------- PTX helpers ----------------------------------------------
__device__ __forceinline__ uint32_t smem_u32(const void* p) {
    uint32_t a;
    asm("{ .reg .u64 t; cvta.to.shared.u64 t, %1; cvt.u32.u64 %0, t; }"
        : "=r"(a) : "l"(p));
    return a;
}
__device__ __forceinline__ void ldsm_x4(uint32_t* r, uint32_t addr) {
    asm volatile("ldmatrix.sync.aligned.m8n8.x4.shared.b16 {%0,%1,%2,%3}, [%4];"
                 : "=r"(r[0]), "=r"(r[1]), "=r"(r[2]), "=r"(r[3]) : "r"(addr));
}
__device__ __forceinline__ void ldsm_x4t(uint32_t* r, uint32_t addr) {
    asm volatile("ldmatrix.sync.aligned.m8n8.x4.trans.shared.b16 {%0,%1,%2,%3}, [%4];"
                 : "=r"(r[0]), "=r"(r[1]), "=r"(r[2]), "=r"(r[3]) : "r"(addr));
}
__device__ __forceinline__ void mma_bf16(float* c, const uint32_t* a,
                                         uint32_t b0, uint32_t b1) {
    asm volatile(
        "mma.sync.aligned.m16n8k16.row.col.f32.bf16.bf16.f32 "
        "{%0,%1,%2,%3}, {%4,%5,%6,%7}, {%8,%9}, {%0,%1,%2,%3};"
        : "+f"(c[0]), "+f"(c[1]), "+f"(c[2]), "+f"(c[3])
        : "r"(a[0]), "r"(a[1]), "r"(a[2]), "r"(a[3]), "r"(b0), "r"(b1));
}
__device__ __forceinline__ uint32_t pack2bf(__nv_bfloat16 a, __nv_bfloat16 b) {
    return (uint32_t)__bfloat16_as_ushort(a) |
           ((uint32_t)__bfloat16_as_ushort(b) << 16);
}

// ---------------- problem constants -----------------------------------------
__host__ __device__ __forceinline__ constexpr int ggrp(int k) {
    return (k < 1) ? 0 : (k < 6) ? 1 : (k < 15) ? 2 : (k < 28) ? 3 : 4;
}
__device__ __forceinline__ float scl_of(int k) {
    const int g = ggrp(k);
    return g == 0 ? 1.77245385090552f
         : g == 1 ? 0.79266545952121f
         : g == 2 ? 0.59081795030184f
         : g == 3 ? 0.49159027f
         :          0.42988321f;
}

// ---------------- setup: split B matrices, expand W -------------------------
__device__ void expand_w(const float* __restrict__ w, float* __restrict__ dst,
                         int CIN, int COUT, int tid) {
    const int n = 5 * CIN * COUT;
    for (int i = tid; i < n; i += NTT) {
        int g = i / (CIN * COUT);
        int r = i - g * (CIN * COUT);
        int c = r / COUT, o = r - c * COUT;
        dst[i] = w[(o * CIN + c) * 5 + g];
    }
}

__global__ void build_B(const float* __restrict__ sft,
                        const float* __restrict__ isft,
                        const float* __restrict__ w1, const float* __restrict__ w2,
                        const float* __restrict__ w3, const float* __restrict__ w4,
                        const float* __restrict__ w5, const float* __restrict__ w6) {
    const int tid = threadIdx.x;
    for (int i = tid; i < 96 * 48; i += NTT) {     // B1[n=p(96)][k(48)]
        int n = i / 48, k = i - n * 48;
        float v = (n < ND && k < NC) ? isft[n * NC + k] : 0.f;
        __nv_bfloat16 hi = __float2bfloat16(v);
        g_B1h[i] = hi;
        g_B1l[i] = __float2bfloat16(v - __bfloat162float(hi));
    }
    for (int i = tid; i < 48 * 96; i += NTT) {     // B2[n=k(48)][k=p(96)]
        int n = i / 96, p = i - n * 96;
        float v = (n < NC && p < ND) ? sft[n * ND + p] : 0.f;
        __nv_bfloat16 hi = __float2bfloat16(v);
        g_B2h[i] = hi;
        g_B2l[i] = __float2bfloat16(v - __bfloat162float(hi));
    }
    expand_w(w1, g_Wexp + 0,     4,  16, tid);
    expand_w(w2, g_Wexp + 320,   16, 32, tid);
    expand_w(w3, g_Wexp + 2880,  32, 64, tid);
    expand_w(w4, g_Wexp + 13120, 64, 32, tid);
    expand_w(w5, g_Wexp + 23360, 32, 16, tid);
    expand_w(w6, g_Wexp + 25920, 16, 4,  tid);
}

// sconv over k in [K0,K0+KN), groups [G0,G0+GN): one thread, FOUR rows
// m0..m0+3 (o = 4*oS+j, same batch element). W via float4 gmem loads.
template <int K0, int KN, int G0, int GN, int CIN, int COUT, int XSTR, int MODE_IN>
__device__ __forceinline__ void sconv_seg4(const float* __restrict__ xb,
                                           const float* __restrict__ wp,
                                           __nv_bfloat16* __restrict__ yh,
                                           __nv_bfloat16* __restrict__ yl,
                                           int m0) {
    constexpr size_t KS = (size_t)NB_TOTAL * CIN;
    float acc[4][KN];
#pragma unroll
    for (int j = 0; j < 4; j++)
#pragma unroll
        for (int kk = 0; kk < KN; kk++) acc[j][kk] = 0.f;

#pragma unroll 1
    for (int cb = 0; cb < CIN; cb += 4) {
        float wq[4][GN][4];
#pragma unroll
        for (int cc = 0; cc < 4; cc++)
#pragma unroll
            for (int gi = 0; gi < GN; gi++) {
                const float4 t = __ldg(reinterpret_cast<const float4*>(
                    wp + (size_t)((G0 + gi) * CIN + cb + cc) * COUT));
                wq[cc][gi][0] = t.x; wq[cc][gi][1] = t.y;
                wq[cc][gi][2] = t.z; wq[cc][gi][3] = t.w;
            }
#pragma unroll
        for (int kk = 0; kk < KN; kk++) {
            float4 xv;
            if constexpr (MODE_IN == 0)
                xv = *reinterpret_cast<const float4*>(xb + (K0 + kk) * XSTR + cb);
            else
                xv = __ldg(reinterpret_cast<const float4*>(
                        xb + (size_t)(K0 + kk) * KS + cb));
            const int gi = ggrp(K0 + kk) - G0;
#pragma unroll
            for (int j = 0; j < 4; j++) {
                acc[j][kk] = fmaf(xv.x, wq[0][gi][j], acc[j][kk]);
                acc[j][kk] = fmaf(xv.y, wq[1][gi][j], acc[j][kk]);
                acc[j][kk] = fmaf(xv.z, wq[2][gi][j], acc[j][kk]);
                acc[j][kk] = fmaf(xv.w, wq[3][gi][j], acc[j][kk]);
            }
        }
    }
#pragma unroll
    for (int kk = 0; kk < KN; kk++) {
        const float s = scl_of(K0 + kk);
        __nv_bfloat16 h[4], l[4];
#pragma unroll
        for (int j = 0; j < 4; j++) {
            const float v = acc[j][kk] * s;
            h[j] = __float2bfloat16(v);
            l[j] = __float2bfloat16(v - __bfloat162float(h[j]));
        }
        uint2 ph, pl;
        ph.x = pack2bf(h[0], h[1]); ph.y = pack2bf(h[2], h[3]);
        pl.x = pack2bf(l[0], l[1]); pl.y = pack2bf(l[2], l[3]);
        *reinterpret_cast<uint2*>(yh + (K0 + kk) * MSTR + m0) = ph;
        *reinterpret_cast<uint2*>(yl + (K0 + kk) * MSTR + m0) = pl;
    }
}

// ---------------- per-layer persistent kernel -------------------------------
template <int CIN, int COUT, int MODE_IN, int MODE_OUT>
__global__ void __launch_bounds__(NTT, 2)
scnn_layer(const float* __restrict__ in, const float* __restrict__ wexp,
           float* __restrict__ out, int ntiles) {
    constexpr int TB   = MTILE / COUT;
    constexpr int MIN_ = TB * CIN;
    constexpr int XSTR = MIN_ + 4;
    constexpr int QTR  = COUT / 4;
    static_assert(MTILE % COUT == 0 && CIN % 4 == 0 && COUT % 4 == 0, "cfg");

    extern __shared__ char smc[];
    const uint32_t sb = smem_u32(smc);
    const int tid = threadIdx.x, wid = tid >> 5, lane = tid & 31;

    __nv_bfloat16* Yh = (__nv_bfloat16*)(smc + OFF_YH);
    __nv_bfloat16* Yl = (__nv_bfloat16*)(smc + OFF_YL);
    float* s_x = (float*)(smc + OFF_X);

    // ---- one-time setup: zero Y region (covers pads), copy B tiles ---------
    for (int i = tid; i < (OFF_X - OFF_YH) / 4; i += NTT)
        ((uint32_t*)(smc + OFF_YH))[i] = 0;
    {
        const uint32_t* s1h = (const uint32_t*)g_B1h;
        const uint32_t* s1l = (const uint32_t*)g_B1l;
        uint32_t* d1h = (uint32_t*)(smc + OFF_B1H);
        uint32_t* d1l = (uint32_t*)(smc + OFF_B1L);
        for (int i = tid; i < 96 * 24; i += NTT) {
            int n = i / 24, kk = i - n * 24;
            d1h[(n * B1STR) / 2 + kk] = s1h[i];
            d1l[(n * B1STR) / 2 + kk] = s1l[i];
        }
        const uint32_t* s2h = (const uint32_t*)g_B2h;
        const uint32_t* s2l = (const uint32_t*)g_B2l;
        uint32_t* d2h = (uint32_t*)(smc + OFF_B2H);
        uint32_t* d2l = (uint32_t*)(smc + OFF_B2L);
        for (int i = tid; i < 48 * 48; i += NTT) {
            int n = i / 48, kk = i - n * 48;
            d2h[(n * B2STR) / 2 + kk] = s2h[i];
            d2l[(n * B2STR) / 2 + kk] = s2l[i];
        }
    }

    // ---- loop-invariant addressing (8 warps, m32 each) ---------------------
    const int mb = wid * 32;
    const int g = lane >> 3, rr = lane & 7;
    const int qr = lane >> 2, qc = lane & 3;

    uint32_t aYt[2];
#pragma unroll
    for (int mt = 0; mt < 2; mt++)
        aYt[mt] = sb + OFF_YH +
            (((g >> 1) * 8 + rr) * MSTR + mb + mt * 16 + (g & 1) * 8) * 2;
    const uint32_t bB1 = sb + OFF_B1H +
        (((g >> 1) * 8 + rr) * B1STR + (g & 1) * 8) * 2;
    const uint32_t bB2 = sb + OFF_B2H +
        (((g >> 1) * 8 + rr) * B2STR + (g & 1) * 8) * 2;

    // sconv mapping: 256 thr = 64 row-quads x 4 k-segments
    const int q   = tid >> 6;              // warp-uniform
    const int idx = tid & 63;
    const int tS  = idx / QTR;
    const int oS  = idx - tS * QTR;
    const int m0S = tS * COUT + 4 * oS;
    const float* wp = wexp + 4 * oS;

    // ---- L1 only: stage first tile's x -------------------------------------
    int t = blockIdx.x;
    if constexpr (MODE_IN == 0) {
        if (t < ntiles) {
            const size_t bi = (size_t)t * (MIN_ * NC);
            for (int i = tid; i < MIN_ * NC; i += NTT) {
                int m = i / NC, k = i - m * NC;
                s_x[k * XSTR + m] = in[bi + i];
            }
        }
    }
    __syncthreads();

    // ---- persistent tile loop ----------------------------------------------
    for (; t < ntiles; t += gridDim.x) {
        // phase A: sconv -> Y[k][m] (4 rows/thread)
        {
            const float* xb;
            if constexpr (MODE_IN == 0) {
                xb = s_x + tS * CIN;
            } else {
                int b = t * TB + tS;
                if (b >= NB_TOTAL) b = NB_TOTAL - 1;   // clamp; store guarded
                xb = in + (size_t)b * CIN;
            }
            if      (q == 0) sconv_seg4< 0, 12, 0, 3, CIN, COUT, XSTR, MODE_IN>(
                                 xb, wp, Yh, Yl, m0S);
            else if (q == 1) sconv_seg4<12, 11, 2, 2, CIN, COUT, XSTR, MODE_IN>(
                                 xb, wp, Yh, Yl, m0S);
            else if (q == 2) sconv_seg4<23, 11, 3, 2, CIN, COUT, XSTR, MODE_IN>(
                                 xb, wp, Yh, Yl, m0S);
            else             sconv_seg4<34, 11, 4, 1, CIN, COUT, XSTR, MODE_IN>(
                                 xb, wp, Yh, Yl, m0S);
        }
        __syncthreads();

        // phase B+C fused: GEMM1 per p16 chunk -> register relu/split -> GEMM2
        uint32_t ah[3][2][4];                       // cached A-hi fragments
#pragma unroll
        for (int ks = 0; ks < 3; ks++)
#pragma unroll
            for (int mt = 0; mt < 2; mt++)
                ldsm_x4t(ah[ks][mt], aYt[mt] + ks * (16 * MSTR * 2));

        float c2[2][6][4];
#pragma unroll
        for (int a = 0; a < 2; a++)
#pragma unroll
            for (int i = 0; i < 6; i++)
#pragma unroll
                for (int j = 0; j < 4; j++) c2[a][i][j] = 0.f;

#pragma unroll
        for (int pc = 0; pc < 6; pc++) {
            float c1t[2][2][4];
#pragma unroll
            for (int a = 0; a < 2; a++)
#pragma unroll
                for (int i = 0; i < 2; i++)
#pragma unroll
                    for (int j = 0; j < 4; j++) c1t[a][i][j] = 0.f;

#pragma unroll
            for (int ks = 0; ks < 3; ks++) {
                uint32_t al[2][4];
#pragma unroll
                for (int mt = 0; mt < 2; mt++)
                    ldsm_x4t(al[mt], aYt[mt] + ks * (16 * MSTR * 2) + DYL);
                const uint32_t bo = bB1 + ks * 32 + pc * (16 * B1STR * 2);
                uint32_t bh[4], bl[4];
                ldsm_x4(bh, bo);
                ldsm_x4(bl, bo + DB1);
#pragma unroll
                for (int mt = 0; mt < 2; mt++) {
                    mma_bf16(c1t[mt][0], ah[ks][mt], bh[0], bh[1]);
                    mma_bf16(c1t[mt][0], ah[ks][mt], bl[0], bl[1]);
                    mma_bf16(c1t[mt][0], al[mt], bh[0], bh[1]);
                    mma_bf16(c1t[mt][1], ah[ks][mt], bh[2], bh[3]);
                    mma_bf16(c1t[mt][1], ah[ks][mt], bl[2], bl[3]);
                    mma_bf16(c1t[mt][1], al[mt], bh[2], bh[3]);
                }
            }
            // repack: relu + hi/lo split, in registers (p16 chunk = GEMM2 k16)
            uint32_t a2h[2][4], a2l[2][4];
#pragma unroll
            for (int mt = 0; mt < 2; mt++)
#pragma unroll
                for (int u = 0; u < 2; u++)
#pragma unroll
                    for (int v = 0; v < 2; v++) {
                        const float p0 = fmaxf(c1t[mt][u][2 * v], 0.f);
                        const float p1 = fmaxf(c1t[mt][u][2 * v + 1], 0.f);
                        const __nv_bfloat16 h0 = __float2bfloat16(p0);
                        const __nv_bfloat16 h1 = __float2bfloat16(p1);
                        a2h[mt][2 * u + v] = pack2bf(h0, h1);
                        a2l[mt][2 * u + v] =
                            pack2bf(__float2bfloat16(p0 - __bfloat162float(h0)),
                                    __float2bfloat16(p1 - __bfloat162float(h1)));
                    }
#pragma unroll
            for (int np = 0; np < 3; np++) {
                const uint32_t bo = bB2 + pc * 32 + np * (16 * B2STR * 2);
                uint32_t bh[4], bl[4];
                ldsm_x4(bh, bo);
                ldsm_x4(bl, bo + DB2);
#pragma unroll
                for (int mt = 0; mt < 2; mt++) {
                    mma_bf16(c2[mt][2 * np], a2h[mt], bh[0], bh[1]);
                    mma_bf16(c2[mt][2 * np], a2h[mt], bl[0], bl[1]);
                    mma_bf16(c2[mt][2 * np], a2l[mt], bh[0], bh[1]);
                    mma_bf16(c2[mt][2 * np + 1], a2h[mt], bh[2], bh[3]);
                    mma_bf16(c2[mt][2 * np + 1], a2h[mt], bl[2], bl[3]);
                    mma_bf16(c2[mt][2 * np + 1], a2l[mt], bh[2], bh[3]);
                }
            }
        }

        // L1 only: prefetch next tile's x (x dead after sconv; after bar1)
        if constexpr (MODE_IN == 0) {
            const int tn = t + gridDim.x;
            if (tn < ntiles) {
                const size_t bi = (size_t)tn * (MIN_ * NC);
                for (int i = tid; i < MIN_ * NC; i += NTT) {
                    int m = i / NC, k = i - m * NC;
                    s_x[k * XSTR + m] = in[bi + i];
                }
            }
        }

        // phase D: store c2 straight to gmem (guarded)
#pragma unroll
        for (int mt = 0; mt < 2; mt++)
#pragma unroll
            for (int j = 0; j < 6; j++) {
                const int col = 8 * j + 2 * qc;
#pragma unroll
                for (int h = 0; h < 2; h++) {
                    const int row = mb + mt * 16 + qr + 8 * h;
                    const float v0 = c2[mt][j][2 * h];
                    const float v1 = c2[mt][j][2 * h + 1];
                    if constexpr (MODE_OUT == 1) {       // [k][b][ch]
                        const int b = t * TB + row / COUT;
                        const int ch = row % COUT;
                        if (b < NB_TOTAL) {
                            if (col < NC)
                                out[((size_t)col * NB_TOTAL + b) * COUT + ch] = v0;
                            if (col + 1 < NC)
                                out[((size_t)(col + 1) * NB_TOTAL + b) * COUT + ch] = v1;
                        }
                    } else {                             // [b][ch][k] (L6)
                        if (t * TB + row / COUT < NB_TOTAL) {
                            const size_t ro = ((size_t)t * MTILE + row) * NC;
                            if (col < NC)     out[ro + col]     = v0;
                            if (col + 1 < NC) out[ro + col + 1] = v1;
                        }
                    }
                }
            }
        __syncthreads();   // protect Y (and L1 s_x) before next tile
    }
}

// ---------------- host ------------------------------------------------------
extern "C" void kernel_launch(void* const* d_in, const int* in_sizes, int n_in,
                              void* d_out, int out_size) {
    (void)in_sizes; (void)n_in; (void)out_size;

    const float* x    = (const float*)d_in[0];
    const float* sft  = (const float*)d_in[1];
    const float* isft = (const float*)d_in[2];
    const float* w1   = (const float*)d_in[3];
    const float* w2   = (const float*)d_in[4];
    const float* w3   = (const float*)d_in[5];
    const float* w4   = (const float*)d_in[6];
    const float* w5   = (const float*)d_in[7];
    const float* w6   = (const float*)d_in[8];
    float* out = (float*)d_out;

    float *bufA = nullptr, *bufB = nullptr, *wexp = nullptr;
    cudaGetSymbolAddress((void**)&bufA, g_bufA);
    cudaGetSymbolAddress((void**)&bufB, g_bufB);
    cudaGetSymbolAddress((void**)&wexp, g_Wexp);

    cudaFuncSetAttribute((const void*)scnn_layer<4, 16, 0, 1>,
        cudaFuncAttributeMaxDynamicSharedMemorySize, smem_total_c(4, 16, 0));
    cudaFuncSetAttribute((const void*)scnn_layer<16, 32, 1, 1>,
        cudaFuncAttributeMaxDynamicSharedMemorySize, smem_total_c(16, 32, 1));
    cudaFuncSetAttribute((const void*)scnn_layer<32, 64, 1, 1>,
        cudaFuncAttributeMaxDynamicSharedMemorySize, smem_total_c(32, 64, 1));
    cudaFuncSetAttribute((const void*)scnn_layer<64, 32, 1, 1>,
        cudaFuncAttributeMaxDynamicSharedMemorySize, smem_total_c(64, 32, 1));
    cudaFuncSetAttribute((const void*)scnn_layer<32, 16, 1, 1>,
        cudaFuncAttributeMaxDynamicSharedMemorySize, smem_total_c(32, 16, 1));
    cudaFuncSetAttribute((const void*)scnn_layer<16, 4, 1, 0>,
        cudaFuncAttributeMaxDynamicSharedMemorySize, smem_total_c(16, 4, 1));

    build_B<<<1, NTT>>>(sft, isft, w1, w2, w3, w4, w5, w6);

    const int GRID2 = 296;   // 2 CTAs/SM
    // TB = 256/COUT -> tiles: L1 3125, L2 6250, L3 12500, L4 6250, L5 3125,
    // L6 ceil(50000/64)=782 (guarded tail)
    scnn_layer<4, 16, 0, 1><<<GRID2, NTT, smem_total_c(4, 16, 0)>>>(
        x, wexp + 0, bufA, NB_TOTAL / 16);
    scnn_layer<16, 32, 1, 1><<<GRID2, NTT, smem_total_c(16, 32, 1)>>>(
        bufA, wexp + 320, bufB, NB_TOTAL / 8);
    scnn_layer<32, 64, 1, 1><<<GRID2, NTT, smem_total_c(32, 64, 1)>>>(
        bufB, wexp + 2880, bufA, NB_TOTAL / 4);
    scnn_layer<64, 32, 1, 1><<<GRID2, NTT, smem_total_c(64, 32, 1)>>>(
        bufA, wexp + 13120, bufB, NB_TOTAL / 8);
    scnn_layer<32, 16, 1, 1><<<GRID2, NTT, smem_total_c(32, 16, 1)>>>(
        bufB, wexp + 23360, bufA, NB_TOTAL / 16);
    scnn_layer<16, 4, 1, 0><<<GRID2, NTT, smem_total_c(16, 4, 1)>>>(
        bufA, wexp + 25920, out, (NB_TOTAL + 63) / 64);
}

// round 16
// speedup vs baseline: 1.6710x; 1.0734x over previous
#include <cuda_runtime.h>
#include <cuda_bf16.h>
#include <cstdint>
#include <cstddef>

// ----------------------------------------------------------------------------
// SCNN via warp-level HMMA (mma.sync bf16, fp32 accum), persistent CTAs.
// R15 = R14 (M=256, 8 warps x m32, pc-fused GEMM1->GEMM2, Wexp gmem, 2 CTA/SM)
// with instruction-count cuts: sconv on fma.rn.f32x2 (row-pair packed),
// bf16 split/pack via cvt.rn.bf16x2.f32, Y scale via mul.rn.f32x2.
// ----------------------------------------------------------------------------

#define NB_TOTAL 50000
#define NC 45
#define ND 90
#define NTT 256
#define MTILE 256
#define MSTR 264     // Y [k][m] row length (256 + 8 pad); 528B rows
#define B1STR  56    // B1 [n=96][k=48], 112B rows
#define B2STR 104    // B2 [n=48][k=96], 208B rows

__device__ float g_bufA[(size_t)NB_TOTAL * 64 * NC];
__device__ float g_bufB[(size_t)NB_TOTAL * 32 * NC];
__device__ __nv_bfloat16 g_B1h[96 * 48], g_B1l[96 * 48];
__device__ __nv_bfloat16 g_B2h[48 * 96], g_B2l[48 * 96];
// Expanded weights, layout [g][c][o] per layer (o contiguous)
__device__ float g_Wexp[26240];
// layer offsets: L1 0, L2 320, L3 2880, L4 13120, L5 23360, L6 25920

// ---------------- smem layout (bytes) ---------------------------------------
#define OFF_B1H 0
#define OFF_B1L 10752
#define OFF_B2H 21504
#define OFF_B2L 31488
#define OFF_YH  41472          /* 48*264*2 = 25344 */
#define OFF_YL  66816
#define OFF_X   92160          /* L1 only */
#define DB1 10752
#define DB2  9984
#define DYL 25344

__host__ __device__ constexpr int smem_total_c(int CIN, int COUT, int MODE_IN) {
    return OFF_X + (MODE_IN == 0 ? NC * ((MTILE / COUT) * CIN + 4) * 4 : 0);
}

// ---------------- PTX helpers ----------------------------------------------
__device__ __forceinline__ uint32_t smem_u32(const void* p) {
    uint32_t a;
    asm("{ .reg .u64 t; cvta.to.shared.u64 t, %1; cvt.u32.u64 %0, t; }"
        : "=r"(a) : "l"(p));
    return a;
}
__device__ __forceinline__ void ldsm_x4(uint32_t* r, uint32_t addr) {
    asm volatile("ldmatrix.sync.aligned.m8n8.x4.shared.b16 {%0,%1,%2,%3}, [%4];"
                 : "=r"(r[0]), "=r"(r[1]), "=r"(r[2]), "=r"(r[3]) : "r"(addr));
}
__device__ __forceinline__ void ldsm_x4t(uint32_t* r, uint32_t addr) {
    asm volatile("ldmatrix.sync.aligned.m8n8.x4.trans.shared.b16 {%0,%1,%2,%3}, [%4];"
                 : "=r"(r[0]), "=r"(r[1]), "=r"(r[2]), "=r"(r[3]) : "r"(addr));
}
__device__ __forceinline__ void mma_bf16(float* c, const uint32_t* a,
                                         uint32_t b0, uint32_t b1) {
    asm volatile(
        "mma.sync.aligned.m16n8k16.row.col.f32.bf16.bf16.f32 "
        "{%0,%1,%2,%3}, {%4,%5,%6,%7}, {%8,%9}, {%0,%1,%2,%3};"
        : "+f"(c[0]), "+f"(c[1]), "+f"(c[2]), "+f"(c[3])
        : "r"(a[0]), "r"(a[1]), "r"(a[2]), "r"(a[3]), "r"(b0), "r"(b1));
}
// packed fp32x2 (base sm_100+ ISA; valid on compute_103 target)
__device__ __forceinline__ uint64_t pk64(float lo, float hi) {
    uint64_t r; asm("mov.b64 %0, {%1, %2};" : "=l"(r) : "f"(lo), "f"(hi));
    return r;
}
__device__ __forceinline__ uint64_t splat64(float v) {
    uint64_t r; asm("mov.b64 %0, {%1, %1};" : "=l"(r) : "f"(v));
    return r;
}
__device__ __forceinline__ void fma64(uint64_t& d, uint64_t a, uint64_t b) {
    asm("fma.rn.f32x2 %0, %1, %2, %0;" : "+l"(d) : "l"(a), "l"(b));
}
__device__ __forceinline__ uint64_t mul64(uint64_t a, uint64_t b) {
    uint64_t r; asm("mul.rn.f32x2 %0, %1, %2;" : "=l"(r) : "l"(a), "l"(b));
    return r;
}
__device__ __forceinline__ void unpk64(float& lo, float& hi, uint64_t v) {
    asm("mov.b64 {%0, %1}, %2;" : "=f"(lo), "=f"(hi) : "l"(v));
}
// packed bf16x2 convert: result = [hi(v1) | lo(v0)], round-to-nearest
__device__ __forceinline__ uint32_t cvt_bf16x2(float v1, float v0) {
    uint32_t r; asm("cvt.rn.bf16x2.f32 %0, %1, %2;" : "=r"(r) : "f"(v1), "f"(v0));
    return r;
}
// split two floats into packed-hi and packed-lo bf16x2 words
__device__ __forceinline__ void split2(float v0, float v1,
                                       uint32_t& hp, uint32_t& lp) {
    hp = cvt_bf16x2(v1, v0);
    const float f0 = __uint_as_float(hp << 16);
    const float f1 = __uint_as_float(hp & 0xFFFF0000u);
    lp = cvt_bf16x2(v1 - f1, v0 - f0);
}

// ---------------- problem constants -----------------------------------------
__host__ __device__ __forceinline__ constexpr int ggrp(int k) {
    return (k < 1) ? 0 : (k < 6) ? 1 : (k < 15) ? 2 : (k < 28) ? 3 : 4;
}
__device__ __forceinline__ float scl_of(int k) {
    const int g = ggrp(k);
    return g == 0 ? 1.77245385090552f
         : g == 1 ? 0.79266545952121f
         : g == 2 ? 0.59081795030184f
         : g == 3 ? 0.49159027f
         :          0.42988321f;
}

// ---------------- setup: split B matrices, expand W -------------------------
__device__ void expand_w(const float* __restrict__ w, float* __restrict__ dst,
                         int CIN, int COUT, int tid) {
    const int n = 5 * CIN * COUT;
    for (int i = tid; i < n; i += NTT) {
        int g = i / (CIN * COUT);
        int r = i - g * (CIN * COUT);
        int c = r / COUT, o = r - c * COUT;
        dst[i] = w[(o * CIN + c) * 5 + g];
    }
}

__global__ void build_B(const float* __restrict__ sft,
                        const float* __restrict__ isft,
                        const float* __restrict__ w1, const float* __restrict__ w2,
                        const float* __restrict__ w3, const float* __restrict__ w4,
                        const float* __restrict__ w5, const float* __restrict__ w6) {
    const int tid = threadIdx.x;
    for (int i = tid; i < 96 * 48; i += NTT) {     // B1[n=p(96)][k(48)]
        int n = i / 48, k = i - n * 48;
        float v = (n < ND && k < NC) ? isft[n * NC + k] : 0.f;
        __nv_bfloat16 hi = __float2bfloat16(v);
        g_B1h[i] = hi;
        g_B1l[i] = __float2bfloat16(v - __bfloat162float(hi));
    }
    for (int i = tid; i < 48 * 96; i += NTT) {     // B2[n=k(48)][k=p(96)]
        int n = i / 96, p = i - n * 96;
        float v = (n < NC && p < ND) ? sft[n * ND + p] : 0.f;
        __nv_bfloat16 hi = __float2bfloat16(v);
        g_B2h[i] = hi;
        g_B2l[i] = __float2bfloat16(v - __bfloat162float(hi));
    }
    expand_w(w1, g_Wexp + 0,     4,  16, tid);
    expand_w(w2, g_Wexp + 320,   16, 32, tid);
    expand_w(w3, g_Wexp + 2880,  32, 64, tid);
    expand_w(w4, g_Wexp + 13120, 64, 32, tid);
    expand_w(w5, g_Wexp + 23360, 32, 16, tid);
    expand_w(w6, g_Wexp + 25920, 16, 4,  tid);
}

// sconv over k in [K0,K0+KN), groups [G0,G0+GN): one thread, FOUR rows
// m0..m0+3, packed as row-pairs in fp32x2 accumulators. W via float4 gmem.
template <int K0, int KN, int G0, int GN, int CIN, int COUT, int XSTR, int MODE_IN>
__device__ __forceinline__ void sconv_seg4(const float* __restrict__ xb,
                                           const float* __restrict__ wp,
                                           __nv_bfloat16* __restrict__ yh,
                                           __nv_bfloat16* __restrict__ yl,
                                           int m0) {
    constexpr size_t KS = (size_t)NB_TOTAL * CIN;
    uint64_t acc2[2][KN];   // jp=0: rows (m0,m0+1); jp=1: rows (m0+2,m0+3)
#pragma unroll
    for (int jp = 0; jp < 2; jp++)
#pragma unroll
        for (int kk = 0; kk < KN; kk++) acc2[jp][kk] = 0ull;

#pragma unroll 1
    for (int cb = 0; cb < CIN; cb += 4) {
        uint64_t w2[4][GN][2];
#pragma unroll
        for (int cc = 0; cc < 4; cc++)
#pragma unroll
            for (int gi = 0; gi < GN; gi++) {
                const float4 t = __ldg(reinterpret_cast<const float4*>(
                    wp + (size_t)((G0 + gi) * CIN + cb + cc) * COUT));
                w2[cc][gi][0] = pk64(t.x, t.y);   // consecutive regs: cheap
                w2[cc][gi][1] = pk64(t.z, t.w);
            }
#pragma unroll
        for (int kk = 0; kk < KN; kk++) {
            float4 xv;
            if constexpr (MODE_IN == 0)
                xv = *reinterpret_cast<const float4*>(xb + (K0 + kk) * XSTR + cb);
            else
                xv = __ldg(reinterpret_cast<const float4*>(
                        xb + (size_t)(K0 + kk) * KS + cb));
            const int gi = ggrp(K0 + kk) - G0;
            const uint64_t x0 = splat64(xv.x), x1 = splat64(xv.y);
            const uint64_t x2 = splat64(xv.z), x3 = splat64(xv.w);
#pragma unroll
            for (int jp = 0; jp < 2; jp++) {
                fma64(acc2[jp][kk], x0, w2[0][gi][jp]);
                fma64(acc2[jp][kk], x1, w2[1][gi][jp]);
                fma64(acc2[jp][kk], x2, w2[2][gi][jp]);
                fma64(acc2[jp][kk], x3, w2[3][gi][jp]);
            }
        }
    }
#pragma unroll
    for (int kk = 0; kk < KN; kk++) {
        const uint64_t s2 = splat64(scl_of(K0 + kk));
        const uint64_t v01 = mul64(acc2[0][kk], s2);
        const uint64_t v23 = mul64(acc2[1][kk], s2);
        float a, b, c, d;
        unpk64(a, b, v01);
        unpk64(c, d, v23);
        uint2 ph, pl;
        split2(a, b, ph.x, pl.x);
        split2(c, d, ph.y, pl.y);
        *reinterpret_cast<uint2*>(yh + (K0 + kk) * MSTR + m0) = ph;
        *reinterpret_cast<uint2*>(yl + (K0 + kk) * MSTR + m0) = pl;
    }
}

// ---------------- per-layer persistent kernel -------------------------------
template <int CIN, int COUT, int MODE_IN, int MODE_OUT>
__global__ void __launch_bounds__(NTT, 2)
scnn_layer(const float* __restrict__ in, const float* __restrict__ wexp,
           float* __restrict__ out, int ntiles) {
    constexpr int TB   = MTILE / COUT;
    constexpr int MIN_ = TB * CIN;
    constexpr int XSTR = MIN_ + 4;
    constexpr int QTR  = COUT / 4;
    static_assert(MTILE % COUT == 0 && CIN % 4 == 0 && COUT % 4 == 0, "cfg");

    extern __shared__ char smc[];
    const uint32_t sb = smem_u32(smc);
    const int tid = threadIdx.x, wid = tid >> 5, lane = tid & 31;

    __nv_bfloat16* Yh = (__nv_bfloat16*)(smc + OFF_YH);
    __nv_bfloat16* Yl = (__nv_bfloat16*)(smc + OFF_YL);
    float* s_x = (float*)(smc + OFF_X);

    // ---- one-time setup: zero Y region (covers pads), copy B tiles ---------
    for (int i = tid; i < (OFF_X - OFF_YH) / 4; i += NTT)
        ((uint32_t*)(smc + OFF_YH))[i] = 0;
    {
        const uint32_t* s1h = (const uint32_t*)g_B1h;
        const uint32_t* s1l = (const uint32_t*)g_B1l;
        uint32_t* d1h = (uint32_t*)(smc + OFF_B1H);
        uint32_t* d1l = (uint32_t*)(smc + OFF_B1L);
        for (int i = tid; i < 96 * 24; i += NTT) {
            int n = i / 24, kk = i - n * 24;
            d1h[(n * B1STR) / 2 + kk] = s1h[i];
            d1l[(n * B1STR) / 2 + kk] = s1l[i];
        }
        const uint32_t* s2h = (const uint32_t*)g_B2h;
        const uint32_t* s2l = (const uint32_t*)g_B2l;
        uint32_t* d2h = (uint32_t*)(smc + OFF_B2H);
        uint32_t* d2l = (uint32_t*)(smc + OFF_B2L);
        for (int i = tid; i < 48 * 48; i += NTT) {
            int n = i / 48, kk = i - n * 48;
            d2h[(n * B2STR) / 2 + kk] = s2h[i];
            d2l[(n * B2STR) / 2 + kk] = s2l[i];
        }
    }

    // ---- loop-invariant addressing (8 warps, m32 each) ---------------------
    const int mb = wid * 32;
    const int g = lane >> 3, rr = lane & 7;
    const int qr = lane >> 2, qc = lane & 3;

    uint32_t aYt[2];
#pragma unroll
    for (int mt = 0; mt < 2; mt++)
        aYt[mt] = sb + OFF_YH +
            (((g >> 1) * 8 + rr) * MSTR + mb + mt * 16 + (g & 1) * 8) * 2;
    const uint32_t bB1 = sb + OFF_B1H +
        (((g >> 1) * 8 + rr) * B1STR + (g & 1) * 8) * 2;
    const uint32_t bB2 = sb + OFF_B2H +
        (((g >> 1) * 8 + rr) * B2STR + (g & 1) * 8) * 2;

    // sconv mapping: 256 thr = 64 row-quads x 4 k-segments
    const int q   = tid >> 6;              // warp-uniform
    const int idx = tid & 63;
    const int tS  = idx / QTR;
    const int oS  = idx - tS * QTR;
    const int m0S = tS * COUT + 4 * oS;
    const float* wp = wexp + 4 * oS;

    // ---- L1 only: stage first tile's x -------------------------------------
    int t = blockIdx.x;
    if constexpr (MODE_IN == 0) {
        if (t < ntiles) {
            const size_t bi = (size_t)t * (MIN_ * NC);
            for (int i = tid; i < MIN_ * NC; i += NTT) {
                int m = i / NC, k = i - m * NC;
                s_x[k * XSTR + m] = in[bi + i];
            }
        }
    }
    __syncthreads();

    // ---- persistent tile loop ----------------------------------------------
    for (; t < ntiles; t += gridDim.x) {
        // phase A: sconv -> Y[k][m] (4 rows/thread, fp32x2 row pairs)
        {
            const float* xb;
            if constexpr (MODE_IN == 0) {
                xb = s_x + tS * CIN;
            } else {
                int b = t * TB + tS;
                if (b >= NB_TOTAL) b = NB_TOTAL - 1;   // clamp; store guarded
                xb = in + (size_t)b * CIN;
            }
            if      (q == 0) sconv_seg4< 0, 12, 0, 3, CIN, COUT, XSTR, MODE_IN>(
                                 xb, wp, Yh, Yl, m0S);
            else if (q == 1) sconv_seg4<12, 11, 2, 2, CIN, COUT, XSTR, MODE_IN>(
                                 xb, wp, Yh, Yl, m0S);
            else if (q == 2) sconv_seg4<23, 11, 3, 2, CIN, COUT, XSTR, MODE_IN>(
                                 xb, wp, Yh, Yl, m0S);
            else             sconv_seg4<34, 11, 4, 1, CIN, COUT, XSTR, MODE_IN>(
                                 xb, wp, Yh, Yl, m0S);
        }
        __syncthreads();

        // phase B+C fused: GEMM1 per p16 chunk -> register relu/split -> GEMM2
        uint32_t ah[3][2][4];                       // cached A-hi fragments
#pragma unroll
        for (int ks = 0; ks < 3; ks++)
#pragma unroll
            for (int mt = 0; mt < 2; mt++)
                ldsm_x4t(ah[ks][mt], aYt[mt] + ks * (16 * MSTR * 2));

        float c2[2][6][4];
#pragma unroll
        for (int a = 0; a < 2; a++)
#pragma unroll
            for (int i = 0; i < 6; i++)
#pragma unroll
                for (int j = 0; j < 4; j++) c2[a][i][j] = 0.f;

#pragma unroll
        for (int pc = 0; pc < 6; pc++) {
            float c1t[2][2][4];
#pragma unroll
            for (int a = 0; a < 2; a++)
#pragma unroll
                for (int i = 0; i < 2; i++)
#pragma unroll
                    for (int j = 0; j < 4; j++) c1t[a][i][j] = 0.f;

#pragma unroll
            for (int ks = 0; ks < 3; ks++) {
                uint32_t al[2][4];
#pragma unroll
                for (int mt = 0; mt < 2; mt++)
                    ldsm_x4t(al[mt], aYt[mt] + ks * (16 * MSTR * 2) + DYL);
                const uint32_t bo = bB1 + ks * 32 + pc * (16 * B1STR * 2);
                uint32_t bh[4], bl[4];
                ldsm_x4(bh, bo);
                ldsm_x4(bl, bo + DB1);
#pragma unroll
                for (int mt = 0; mt < 2; mt++) {
                    mma_bf16(c1t[mt][0], ah[ks][mt], bh[0], bh[1]);
                    mma_bf16(c1t[mt][0], ah[ks][mt], bl[0], bl[1]);
                    mma_bf16(c1t[mt][0], al[mt], bh[0], bh[1]);
                    mma_bf16(c1t[mt][1], ah[ks][mt], bh[2], bh[3]);
                    mma_bf16(c1t[mt][1], ah[ks][mt], bl[2], bl[3]);
                    mma_bf16(c1t[mt][1], al[mt], bh[2], bh[3]);
                }
            }
            // repack: relu + hi/lo split (packed bf16x2 cvt), in registers
            uint32_t a2h[2][4], a2l[2][4];
#pragma unroll
            for (int mt = 0; mt < 2; mt++)
#pragma unroll
                for (int u = 0; u < 2; u++)
#pragma unroll
                    for (int v = 0; v < 2; v++) {
                        const float p0 = fmaxf(c1t[mt][u][2 * v], 0.f);
                        const float p1 = fmaxf(c1t[mt][u][2 * v + 1], 0.f);
                        split2(p0, p1, a2h[mt][2 * u + v], a2l[mt][2 * u + v]);
                    }
#pragma unroll
            for (int np = 0; np < 3; np++) {
                const uint32_t bo = bB2 + pc * 32 + np * (16 * B2STR * 2);
                uint32_t bh[4], bl[4];
                ldsm_x4(bh, bo);
                ldsm_x4(bl, bo + DB2);
#pragma unroll
                for (int mt = 0; mt < 2; mt++) {
                    mma_bf16(c2[mt][2 * np], a2h[mt], bh[0], bh[1]);
                    mma_bf16(c2[mt][2 * np], a2h[mt], bl[0], bl[1]);
                    mma_bf16(c2[mt][2 * np], a2l[mt], bh[0], bh[1]);
                    mma_bf16(c2[mt][2 * np + 1], a2h[mt], bh[2], bh[3]);
                    mma_bf16(c2[mt][2 * np + 1], a2h[mt], bl[2], bl[3]);
                    mma_bf16(c2[mt][2 * np + 1], a2l[mt], bh[2], bh[3]);
                }
            }
        }

        // L1 only: prefetch next tile's x (x dead after sconv; after bar1)
        if constexpr (MODE_IN == 0) {
            const int tn = t + gridDim.x;
            if (tn < ntiles) {
                const size_t bi = (size_t)tn * (MIN_ * NC);
                for (int i = tid; i < MIN_ * NC; i += NTT) {
                    int m = i / NC, k = i - m * NC;
                    s_x[k * XSTR + m] = in[bi + i];
                }
            }
        }

        // phase D: store c2 straight to gmem (guarded)
#pragma unroll
        for (int mt = 0; mt < 2; mt++)
#pragma unroll
            for (int j = 0; j < 6; j++) {
                const int col = 8 * j + 2 * qc;
#pragma unroll
                for (int h = 0; h < 2; h++) {
                    const int row = mb + mt * 16 + qr + 8 * h;
                    const float v0 = c2[mt][j][2 * h];
                    const float v1 = c2[mt][j][2 * h + 1];
                    if constexpr (MODE_OUT == 1) {       // [k][b][ch]
                        const int b = t * TB + row / COUT;
                        const int ch = row % COUT;
                        if (b < NB_TOTAL) {
                            if (col < NC)
                                out[((size_t)col * NB_TOTAL + b) * COUT + ch] = v0;
                            if (col + 1 < NC)
                                out[((size_t)(col + 1) * NB_TOTAL + b) * COUT + ch] = v1;
                        }
                    } else {                             // [b][ch][k] (L6)
                        if (t * TB + row / COUT < NB_TOTAL) {
                            const size_t ro = ((size_t)t * MTILE + row) * NC;
                            if (col < NC)     out[ro + col]     = v0;
                            if (col + 1 < NC) out[ro + col + 1] = v1;
                        }
                    }
                }
            }
        __syncthreads();   // protect Y (and L1 s_x) before next tile
    }
}

// ---------------- host ------------------------------------------------------
extern "C" void kernel_launch(void* const* d_in, const int* in_sizes, int n_in,
                              void* d_out, int out_size) {
    (void)in_sizes; (void)n_in; (void)out_size;

    const float* x    = (const float*)d_in[0];
    const float* sft  = (const float*)d_in[1];
    const float* isft = (const float*)d_in[2];
    const float* w1   = (const float*)d_in[3];
    const float* w2   = (const float*)d_in[4];
    const float* w3   = (const float*)d_in[5];
    const float* w4   = (const float*)d_in[6];
    const float* w5   = (const float*)d_in[7];
    const float* w6   = (const float*)d_in[8];
    float* out = (float*)d_out;

    float *bufA = nullptr, *bufB = nullptr, *wexp = nullptr;
    cudaGetSymbolAddress((void**)&bufA, g_bufA);
    cudaGetSymbolAddress((void**)&bufB, g_bufB);
    cudaGetSymbolAddress((void**)&wexp, g_Wexp);

    cudaFuncSetAttribute((const void*)scnn_layer<4, 16, 0, 1>,
        cudaFuncAttributeMaxDynamicSharedMemorySize, smem_total_c(4, 16, 0));
    cudaFuncSetAttribute((const void*)scnn_layer<16, 32, 1, 1>,
        cudaFuncAttributeMaxDynamicSharedMemorySize, smem_total_c(16, 32, 1));
    cudaFuncSetAttribute((const void*)scnn_layer<32, 64, 1, 1>,
        cudaFuncAttributeMaxDynamicSharedMemorySize, smem_total_c(32, 64, 1));
    cudaFuncSetAttribute((const void*)scnn_layer<64, 32, 1, 1>,
        cudaFuncAttributeMaxDynamicSharedMemorySize, smem_total_c(64, 32, 1));
    cudaFuncSetAttribute((const void*)scnn_layer<32, 16, 1, 1>,
        cudaFuncAttributeMaxDynamicSharedMemorySize, smem_total_c(32, 16, 1));
    cudaFuncSetAttribute((const void*)scnn_layer<16, 4, 1, 0>,
        cudaFuncAttributeMaxDynamicSharedMemorySize, smem_total_c(16, 4, 1));

    build_B<<<1, NTT>>>(sft, isft, w1, w2, w3, w4, w5, w6);

    const int GRID2 = 296;   // 2 CTAs/SM
    scnn_layer<4, 16, 0, 1><<<GRID2, NTT, smem_total_c(4, 16, 0)>>>(
        x, wexp + 0, bufA, NB_TOTAL / 16);
    scnn_layer<16, 32, 1, 1><<<GRID2, NTT, smem_total_c(16, 32, 1)>>>(
        bufA, wexp + 320, bufB, NB_TOTAL / 8);
    scnn_layer<32, 64, 1, 1><<<GRID2, NTT, smem_total_c(32, 64, 1)>>>(
        bufB, wexp + 2880, bufA, NB_TOTAL / 4);
    scnn_layer<64, 32, 1, 1><<<GRID2, NTT, smem_total_c(64, 32, 1)>>>(
        bufA, wexp + 13120, bufB, NB_TOTAL / 8);
    scnn_layer<32, 16, 1, 1><<<GRID2, NTT, smem_total_c(32, 16, 1)>>>(
        bufB, wexp + 23360, bufA, NB_TOTAL / 16);
    scnn_layer<16, 4, 1, 0><<<GRID2, NTT, smem_total_c(16, 4, 1)>>>(
        bufA, wexp + 25920, out, (NB_TOTAL + 63) / 64);
}